// round 2
// baseline (speedup 1.0000x reference)
#include <cuda_runtime.h>
#include <math.h>

#define BATCH  2
#define SEQ    2048
#define DMODEL 1024
#define DINNER 2048
#define DSTATE 16
#define DTRANK 64
#define NTOK   (BATCH*SEQ)     /* 4096 tokens */
#define XDN    96              /* dt_rank + 2*d_state */

// ---------------- scratch (static device globals; no allocation) ----------
__device__ float g_xn[NTOK*DMODEL];            // 16 MB
__device__ float g_xz[NTOK*2*DINNER];          // 64 MB
__device__ float g_u[NTOK*DINNER];             // 32 MB
__device__ float g_xdbl[NTOK*XDN];             // 1.5 MB
__device__ float g_delta[NTOK*DINNER];         // 32 MB
__device__ float g_y[NTOK*DINNER];             // 32 MB

// ---------------- helpers ----------------
__device__ __forceinline__ float softplus_f(float x){
    return (x > 20.f) ? x : log1pf(expf(x));
}
__device__ __forceinline__ float gelu_f(float x){
    return 0.5f * x * (1.f + erff(x * 0.70710678118654752440f));
}
__device__ __forceinline__ float silu_f(float x){
    return x * (1.f / (1.f + __expf(-x)));
}

// ---------------- LayerNorm: one block per token ----------------
__global__ void __launch_bounds__(256) ln_kernel(const float* __restrict__ x,
                                                 const float* __restrict__ w,
                                                 const float* __restrict__ b,
                                                 float* __restrict__ out)
{
    int row = blockIdx.x;
    int tid = threadIdx.x;
    const float4* xr = reinterpret_cast<const float4*>(x + (size_t)row*DMODEL);
    float4 v = xr[tid];
    float s = v.x+v.y+v.z+v.w;
    float q = v.x*v.x+v.y*v.y+v.z*v.z+v.w*v.w;
    #pragma unroll
    for (int o=16;o>0;o>>=1){
        s += __shfl_down_sync(0xffffffffu, s, o);
        q += __shfl_down_sync(0xffffffffu, q, o);
    }
    __shared__ float ss[8], sq[8];
    __shared__ float mu_s, inv_s;
    int wp = tid>>5, ln = tid&31;
    if (ln==0){ ss[wp]=s; sq[wp]=q; }
    __syncthreads();
    if (tid==0){
        float ts=0.f, tq=0.f;
        #pragma unroll
        for (int i=0;i<8;i++){ ts+=ss[i]; tq+=sq[i]; }
        float mu  = ts * (1.f/DMODEL);
        float var = tq * (1.f/DMODEL) - mu*mu;
        mu_s = mu; inv_s = rsqrtf(var + 1e-5f);
    }
    __syncthreads();
    float mu = mu_s, inv = inv_s;
    float4 wv = reinterpret_cast<const float4*>(w)[tid];
    float4 bv = reinterpret_cast<const float4*>(b)[tid];
    float4 o;
    o.x = (v.x-mu)*inv*wv.x + bv.x;
    o.y = (v.y-mu)*inv*wv.y + bv.y;
    o.z = (v.z-mu)*inv*wv.z + bv.z;
    o.w = (v.w-mu)*inv*wv.w + bv.w;
    reinterpret_cast<float4*>(out + (size_t)row*DMODEL)[tid] = o;
}

// ---------------- SGEMM 128x128x8, 256 threads, 8x8 per thread -----------
// C[M,N] = A[M,K] @ B[K,N], all row-major, M,N multiples of 128, K mult of 8.
// EPI: 0 = plain, 1 = softplus(acc + bias[col]), 2 = gelu(acc) + res[row,col]
template<int EPI>
__global__ void __launch_bounds__(256) sgemm128(const float* __restrict__ A,
                                                const float* __restrict__ B,
                                                float* __restrict__ C,
                                                int M, int N, int K,
                                                int lda, int ldb, int ldc,
                                                const float* __restrict__ bias,
                                                const float* __restrict__ res,
                                                int ldres)
{
    __shared__ float As[8][128];
    __shared__ float Bs[8][128];
    const int tid = threadIdx.x;
    const int bm = blockIdx.y*128, bn = blockIdx.x*128;
    const int ty = tid>>4, tx = tid&15;
    const int arow = tid>>1,  acol = (tid&1)*4;
    const int brow = tid>>5,  bcol = (tid&31)*4;

    const float* Ap = A + (size_t)(bm+arow)*lda + acol;   // +k along row
    const float* Bp = B + (size_t)brow*ldb + bn + bcol;   // +k*ldb down

    float4 af = *(const float4*)Ap;
    float4 bf = *(const float4*)Bp;

    float acc[8][8];
    #pragma unroll
    for (int i=0;i<8;i++)
        #pragma unroll
        for (int j=0;j<8;j++) acc[i][j]=0.f;

    for (int k0=0; k0<K; k0+=8){
        As[acol+0][arow]=af.x; As[acol+1][arow]=af.y;
        As[acol+2][arow]=af.z; As[acol+3][arow]=af.w;
        *(float4*)&Bs[brow][bcol] = bf;
        __syncthreads();
        if (k0+8 < K){
            af = *(const float4*)(Ap + (k0+8));
            bf = *(const float4*)(Bp + (size_t)(k0+8)*ldb);
        }
        #pragma unroll
        for (int k=0;k<8;k++){
            float ar[8], br[8];
            *(float4*)&ar[0] = *(const float4*)&As[k][ty*8];
            *(float4*)&ar[4] = *(const float4*)&As[k][ty*8+4];
            *(float4*)&br[0] = *(const float4*)&Bs[k][tx*8];
            *(float4*)&br[4] = *(const float4*)&Bs[k][tx*8+4];
            #pragma unroll
            for (int i=0;i<8;i++)
                #pragma unroll
                for (int j=0;j<8;j++)
                    acc[i][j] = fmaf(ar[i], br[j], acc[i][j]);
        }
        __syncthreads();
    }

    #pragma unroll
    for (int i=0;i<8;i++){
        int r = bm + ty*8 + i;
        float vals[8];
        #pragma unroll
        for (int j=0;j<8;j++){
            float v = acc[i][j];
            int c = bn + tx*8 + j;
            if (EPI==1)      v = softplus_f(v + bias[c]);
            else if (EPI==2) v = gelu_f(v) + res[(size_t)r*ldres + c];
            vals[j] = v;
        }
        float* cp = C + (size_t)r*ldc + bn + tx*8;
        *(float4*)cp     = *(float4*)&vals[0];
        *(float4*)(cp+4) = *(float4*)&vals[4];
    }
}

// ---------------- depthwise causal conv (width 4) + SiLU -----------------
// u[b,t,d] = silu( sum_j xz[b, t-3+j, d] * conv_w[d, j] + conv_b[d] )
__global__ void __launch_bounds__(256) conv_silu_kernel(const float* __restrict__ xz,
                                                        const float* __restrict__ cw,
                                                        const float* __restrict__ cb,
                                                        float* __restrict__ u)
{
    int lin = blockIdx.x*256 + threadIdx.x;        // over NTOK * DINNER/4
    int d4  = lin & (DINNER/4 - 1);
    int tok = lin >> 9;                            // DINNER/4 = 512
    int t   = tok & (SEQ-1);
    int d   = d4*4;

    float4 acc = *(const float4*)(cb + d);
    float w0[4], w1[4], w2[4], w3[4];
    *(float4*)w0 = *(const float4*)(cw + (size_t)(d+0)*4);
    *(float4*)w1 = *(const float4*)(cw + (size_t)(d+1)*4);
    *(float4*)w2 = *(const float4*)(cw + (size_t)(d+2)*4);
    *(float4*)w3 = *(const float4*)(cw + (size_t)(d+3)*4);

    const float* base = xz + (size_t)tok*(2*DINNER) + d;
    #pragma unroll
    for (int j=0;j<4;j++){
        int tt = t - 3 + j;
        if (tt >= 0){
            float4 xv = *(const float4*)(base + (ptrdiff_t)(j-3)*(2*DINNER));
            acc.x = fmaf(xv.x, w0[j], acc.x);
            acc.y = fmaf(xv.y, w1[j], acc.y);
            acc.z = fmaf(xv.z, w2[j], acc.z);
            acc.w = fmaf(xv.w, w3[j], acc.w);
        }
    }
    float4 o;
    o.x = silu_f(acc.x); o.y = silu_f(acc.y);
    o.z = silu_f(acc.z); o.w = silu_f(acc.w);
    *(float4*)(u + (size_t)tok*DINNER + d) = o;
}

// ---------------- skinny GEMM: x_dbl = u @ W_x  (4096 x 96 x 2048) -------
__global__ void __launch_bounds__(256) gemm_xdbl_kernel(const float* __restrict__ A,
                                                        const float* __restrict__ B,
                                                        float* __restrict__ C)
{
    __shared__ float As[32][65];
    __shared__ float Bs[32][100];
    int tid = threadIdx.x;
    int bm  = blockIdx.x*64;
    int ty  = tid>>4, tx = tid&15;
    float acc[4][6];
    #pragma unroll
    for (int i=0;i<4;i++)
        #pragma unroll
        for (int j=0;j<6;j++) acc[i][j]=0.f;

    for (int k0=0;k0<DINNER;k0+=32){
        #pragma unroll
        for (int i=0;i<2;i++){
            int lin = tid + i*256;                 // 512 float4 of A tile
            int m = lin>>3, k4 = (lin&7)*4;
            float4 v = *(const float4*)(A + (size_t)(bm+m)*DINNER + k0 + k4);
            As[k4+0][m]=v.x; As[k4+1][m]=v.y; As[k4+2][m]=v.z; As[k4+3][m]=v.w;
        }
        #pragma unroll
        for (int i=0;i<3;i++){
            int lin = tid + i*256;                 // 768 float4 of B tile
            int kr = lin/24, c4 = (lin%24)*4;
            float4 v = *(const float4*)(B + (size_t)(k0+kr)*XDN + c4);
            *(float4*)&Bs[kr][c4] = v;
        }
        __syncthreads();
        #pragma unroll
        for (int k=0;k<32;k++){
            float a[4], bb[6];
            #pragma unroll
            for (int i=0;i<4;i++) a[i]=As[k][ty*4+i];
            #pragma unroll
            for (int j=0;j<6;j++) bb[j]=Bs[k][tx*6+j];
            #pragma unroll
            for (int i=0;i<4;i++)
                #pragma unroll
                for (int j=0;j<6;j++)
                    acc[i][j] = fmaf(a[i], bb[j], acc[i][j]);
        }
        __syncthreads();
    }
    #pragma unroll
    for (int i=0;i<4;i++)
        #pragma unroll
        for (int j=0;j<6;j++)
            C[(size_t)(bm+ty*4+i)*XDN + tx*6 + j] = acc[i][j];
}

// ---------------- selective scan (fused gating output) -------------------
// Warp layout: lanes 0-15 = states of channel d0, lanes 16-31 = channel d0+1.
// y[b,t,d] = (C_t . h_t + u*D) * silu(z)
__global__ void __launch_bounds__(256) scan_kernel(const float* __restrict__ delta,
                                                   const float* __restrict__ u,
                                                   const float* __restrict__ xdbl,
                                                   const float* __restrict__ xz,
                                                   const float* __restrict__ A_log,
                                                   const float* __restrict__ D_skip,
                                                   float* __restrict__ y)
{
    int b    = blockIdx.y;
    int tid  = threadIdx.x;
    int warp = tid>>5;
    int lane = tid&31;
    int half = lane>>4;
    int s    = lane&15;
    int d    = blockIdx.x*16 + warp*2 + half;

    float Aval = -expf(A_log[(size_t)d*DSTATE + s]);
    float Dv   = D_skip[d];

    const float* drow = delta + (size_t)b*SEQ*DINNER + d;
    const float* urow = u     + (size_t)b*SEQ*DINNER + d;
    const float* zrow = xz    + (size_t)b*SEQ*(2*DINNER) + DINNER + d;
    const float* xb   = xdbl  + (size_t)b*SEQ*XDN + DTRANK + s;
    float*       yrow = y     + (size_t)b*SEQ*DINNER + d;

    float h = 0.f;
    for (int t=0; t<SEQ; t++){
        float dlt = __ldg(drow + (size_t)t*DINNER);
        float uu  = __ldg(urow + (size_t)t*DINNER);
        float Bv  = __ldg(xb + (size_t)t*XDN);
        float Cv  = __ldg(xb + (size_t)t*XDN + DSTATE);
        float dA  = __expf(dlt * Aval);
        h = fmaf(dA, h, (dlt*uu)*Bv);
        float yp = h * Cv;
        yp += __shfl_xor_sync(0xffffffffu, yp, 1);
        yp += __shfl_xor_sync(0xffffffffu, yp, 2);
        yp += __shfl_xor_sync(0xffffffffu, yp, 4);
        yp += __shfl_xor_sync(0xffffffffu, yp, 8);
        if (s == 0){
            float zz = __ldg(zrow + (size_t)t*(2*DINNER));
            yrow[(size_t)t*DINNER] = (yp + uu*Dv) * silu_f(zz);
        }
    }
}

// ---------------- launch ----------------
extern "C" void kernel_launch(void* const* d_in, const int* in_sizes, int n_in,
                              void* d_out, int out_size)
{
    const float* x      = (const float*)d_in[0];
    const float* ln_w   = (const float*)d_in[1];
    const float* ln_b   = (const float*)d_in[2];
    const float* W_in   = (const float*)d_in[3];
    const float* conv_w = (const float*)d_in[4];
    const float* conv_b = (const float*)d_in[5];
    const float* W_x    = (const float*)d_in[6];
    const float* W_dt   = (const float*)d_in[7];
    const float* b_dt   = (const float*)d_in[8];
    const float* A_log  = (const float*)d_in[9];
    const float* D_skip = (const float*)d_in[10];
    const float* W_out  = (const float*)d_in[11];
    float* out = (float*)d_out;

    float *xn, *xz, *u, *xdbl, *delta, *y;
    cudaGetSymbolAddress((void**)&xn,    g_xn);
    cudaGetSymbolAddress((void**)&xz,    g_xz);
    cudaGetSymbolAddress((void**)&u,     g_u);
    cudaGetSymbolAddress((void**)&xdbl,  g_xdbl);
    cudaGetSymbolAddress((void**)&delta, g_delta);
    cudaGetSymbolAddress((void**)&y,     g_y);

    // 1) LayerNorm
    ln_kernel<<<NTOK, 256>>>(x, ln_w, ln_b, xn);

    // 2) xz = xn @ W_in   [4096 x 4096 x 1024]
    sgemm128<0><<<dim3((2*DINNER)/128, NTOK/128), 256>>>(
        xn, W_in, xz, NTOK, 2*DINNER, DMODEL, DMODEL, 2*DINNER, 2*DINNER,
        nullptr, nullptr, 0);

    // 3) depthwise causal conv + silu -> u
    conv_silu_kernel<<<(NTOK*(DINNER/4))/256, 256>>>(xz, conv_w, conv_b, u);

    // 4) x_dbl = u @ W_x  [4096 x 96 x 2048]
    gemm_xdbl_kernel<<<NTOK/64, 256>>>(u, W_x, xdbl);

    // 5) delta = softplus(dt @ W_dt + b_dt)  [4096 x 2048 x 64], dt = x_dbl[:, :64]
    sgemm128<1><<<dim3(DINNER/128, NTOK/128), 256>>>(
        xdbl, W_dt, delta, NTOK, DINNER, DTRANK, XDN, DINNER, DINNER,
        b_dt, nullptr, 0);

    // 6) selective scan + gating -> y
    scan_kernel<<<dim3(DINNER/16, BATCH), 256>>>(delta, u, xdbl, xz, A_log, D_skip, y);

    // 7) out = gelu(y @ W_out) + x  [4096 x 1024 x 2048]
    sgemm128<2><<<dim3(DMODEL/128, NTOK/128), 256>>>(
        y, W_out, out, NTOK, DMODEL, DINNER, DINNER, DMODEL, DMODEL,
        nullptr, x, DMODEL);
}

// round 3
// speedup vs baseline: 1.3040x; 1.3040x over previous
#include <cuda_runtime.h>
#include <math.h>

#define BATCH  2
#define SEQ    2048
#define DMODEL 1024
#define DINNER 2048
#define DSTATE 16
#define DTRANK 64
#define NTOK   (BATCH*SEQ)     /* 4096 tokens */
#define XDN    96              /* dt_rank + 2*d_state */

// ---------------- scratch (static device globals; no allocation) ----------
__device__ float g_xn[NTOK*DMODEL];            // 16 MB
__device__ float g_xz[NTOK*2*DINNER];          // 64 MB
__device__ float g_u[NTOK*DINNER];             // 32 MB
__device__ float g_xdbl[NTOK*XDN];             // 1.5 MB
__device__ float g_delta[NTOK*DINNER];         // 32 MB
__device__ float g_y[NTOK*DINNER];             // 32 MB

// ---------------- helpers ----------------
__device__ __forceinline__ float softplus_f(float x){
    return (x > 20.f) ? x : log1pf(expf(x));
}
__device__ __forceinline__ float gelu_f(float x){
    return 0.5f * x * (1.f + erff(x * 0.70710678118654752440f));
}
__device__ __forceinline__ float silu_f(float x){
    return x * (1.f / (1.f + __expf(-x)));
}
__device__ __forceinline__ unsigned f2tf(float x){
    unsigned u; asm("cvt.rna.tf32.f32 %0, %1;" : "=r"(u) : "f"(x)); return u;
}
__device__ __forceinline__ void mma_tf32(float c[4], const unsigned a[4], const unsigned b[2]){
    asm volatile("mma.sync.aligned.m16n8k8.row.col.f32.tf32.tf32.f32 "
        "{%0,%1,%2,%3},{%4,%5,%6,%7},{%8,%9},{%0,%1,%2,%3};"
        : "+f"(c[0]), "+f"(c[1]), "+f"(c[2]), "+f"(c[3])
        : "r"(a[0]), "r"(a[1]), "r"(a[2]), "r"(a[3]), "r"(b[0]), "r"(b[1]));
}
__device__ __forceinline__ void cp16(float* smem, const float* g){
    unsigned saddr = (unsigned)__cvta_generic_to_shared(smem);
    asm volatile("cp.async.cg.shared.global [%0], [%1], 16;\n" :: "r"(saddr), "l"(g));
}
__device__ __forceinline__ void cp_commit(){ asm volatile("cp.async.commit_group;\n"); }
__device__ __forceinline__ void cp_wait1(){ asm volatile("cp.async.wait_group 1;\n"); }

// ---------------- LayerNorm: one block per token ----------------
__global__ void __launch_bounds__(256) ln_kernel(const float* __restrict__ x,
                                                 const float* __restrict__ w,
                                                 const float* __restrict__ b,
                                                 float* __restrict__ out)
{
    int row = blockIdx.x;
    int tid = threadIdx.x;
    const float4* xr = reinterpret_cast<const float4*>(x + (size_t)row*DMODEL);
    float4 v = xr[tid];
    float s = v.x+v.y+v.z+v.w;
    float q = v.x*v.x+v.y*v.y+v.z*v.z+v.w*v.w;
    #pragma unroll
    for (int o=16;o>0;o>>=1){
        s += __shfl_down_sync(0xffffffffu, s, o);
        q += __shfl_down_sync(0xffffffffu, q, o);
    }
    __shared__ float ss[8], sq[8];
    __shared__ float mu_s, inv_s;
    int wp = tid>>5, ln = tid&31;
    if (ln==0){ ss[wp]=s; sq[wp]=q; }
    __syncthreads();
    if (tid==0){
        float ts=0.f, tq=0.f;
        #pragma unroll
        for (int i=0;i<8;i++){ ts+=ss[i]; tq+=sq[i]; }
        float mu  = ts * (1.f/DMODEL);
        float var = tq * (1.f/DMODEL) - mu*mu;
        mu_s = mu; inv_s = rsqrtf(var + 1e-5f);
    }
    __syncthreads();
    float mu = mu_s, inv = inv_s;
    float4 wv = reinterpret_cast<const float4*>(w)[tid];
    float4 bv = reinterpret_cast<const float4*>(b)[tid];
    float4 o;
    o.x = (v.x-mu)*inv*wv.x + bv.x;
    o.y = (v.y-mu)*inv*wv.y + bv.y;
    o.z = (v.z-mu)*inv*wv.z + bv.z;
    o.w = (v.w-mu)*inv*wv.w + bv.w;
    reinterpret_cast<float4*>(out + (size_t)row*DMODEL)[tid] = o;
}

// ================== TF32 tensor-core GEMM 128x128, 8 warps ================
// C[M,N] = A[M,K] @ B[K,N], row-major. M,N mult of 128, K mult of 16.
// EPI: 0 = plain, 2 = gelu(acc) + res[row,col]
#define AS_LD 20
#define BS_LD 136

template<int EPI>
__global__ void __launch_bounds__(256,2) tf32gemm(const float* __restrict__ A,
                                                  const float* __restrict__ B,
                                                  float* __restrict__ C,
                                                  int M, int N, int K,
                                                  int lda, int ldb, int ldc,
                                                  const float* __restrict__ res,
                                                  int ldres)
{
    __shared__ float As[2][128*AS_LD];
    __shared__ float Bs[2][16*BS_LD];

    const int tid  = threadIdx.x;
    const int warp = tid>>5, lane = tid&31;
    const int wm = warp>>2, wn = warp&3;        // 2 x 4 warp grid
    const int g  = lane>>2, tg = lane&3;
    const int bm = blockIdx.y*128, bn = blockIdx.x*128;

    // staging indices (2 chunks of 16B per thread per tile)
    const float* aptr[2]; int asm_[2];
    const float* bptr[2]; int bsm_[2];
    #pragma unroll
    for (int s=0;s<2;s++){
        int c  = tid + s*256;
        int m  = c>>2, k4 = (c&3)*4;
        aptr[s] = A + (size_t)(bm+m)*lda + k4;
        asm_[s] = m*AS_LD + k4;
        int kr = c>>5, n4 = (c&31)*4;
        bptr[s] = B + (size_t)kr*ldb + bn + n4;
        bsm_[s] = kr*BS_LD + n4;
    }

    float acc[4][4][4];
    #pragma unroll
    for (int i=0;i<4;i++)
        #pragma unroll
        for (int j=0;j<4;j++)
            #pragma unroll
            for (int r=0;r<4;r++) acc[i][j][r]=0.f;

    const int nkt = K/16;
    // prologue: stages 0 and 1
    #pragma unroll
    for (int st=0; st<2; st++){
        int k0 = st*16;
        #pragma unroll
        for (int s=0;s<2;s++){
            cp16(&As[st][asm_[s]], aptr[s] + k0);
            cp16(&Bs[st][bsm_[s]], bptr[s] + (size_t)k0*ldb);
        }
        cp_commit();
    }

    for (int kt=0; kt<nkt; kt++){
        cp_wait1();
        __syncthreads();
        int buf = kt & 1;
        const float* as = As[buf];
        const float* bs = Bs[buf];
        #pragma unroll
        for (int kg=0; kg<16; kg+=8){
            unsigned af[4][4], bf[4][2];
            #pragma unroll
            for (int i=0;i<4;i++){
                int mr = wm*64 + i*16 + g;
                af[i][0] = f2tf(as[ mr   *AS_LD + kg+tg  ]);
                af[i][1] = f2tf(as[(mr+8)*AS_LD + kg+tg  ]);
                af[i][2] = f2tf(as[ mr   *AS_LD + kg+tg+4]);
                af[i][3] = f2tf(as[(mr+8)*AS_LD + kg+tg+4]);
            }
            #pragma unroll
            for (int j=0;j<4;j++){
                int nc = wn*32 + j*8 + g;
                bf[j][0] = f2tf(bs[(kg+tg  )*BS_LD + nc]);
                bf[j][1] = f2tf(bs[(kg+tg+4)*BS_LD + nc]);
            }
            #pragma unroll
            for (int i=0;i<4;i++)
                #pragma unroll
                for (int j=0;j<4;j++)
                    mma_tf32(acc[i][j], af[i], bf[j]);
        }
        __syncthreads();
        if (kt+2 < nkt){
            int k0 = (kt+2)*16;
            #pragma unroll
            for (int s=0;s<2;s++){
                cp16(&As[buf][asm_[s]], aptr[s] + k0);
                cp16(&Bs[buf][bsm_[s]], bptr[s] + (size_t)k0*ldb);
            }
        }
        cp_commit();
    }

    // epilogue
    #pragma unroll
    for (int i=0;i<4;i++){
        #pragma unroll
        for (int j=0;j<4;j++){
            int r = bm + wm*64 + i*16 + g;
            int c = bn + wn*32 + j*8 + tg*2;
            float v0=acc[i][j][0], v1=acc[i][j][1];
            float v2=acc[i][j][2], v3=acc[i][j][3];
            if (EPI==2){
                v0 = gelu_f(v0) + res[(size_t)r*ldres + c];
                v1 = gelu_f(v1) + res[(size_t)r*ldres + c + 1];
                v2 = gelu_f(v2) + res[(size_t)(r+8)*ldres + c];
                v3 = gelu_f(v3) + res[(size_t)(r+8)*ldres + c + 1];
            }
            float2 p0 = make_float2(v0,v1);
            float2 p1 = make_float2(v2,v3);
            *(float2*)(C + (size_t)r*ldc + c)     = p0;
            *(float2*)(C + (size_t)(r+8)*ldc + c) = p1;
        }
    }
}

// ---------------- SGEMM 128x128x8 fp32 (kept for the delta GEMM) ---------
// EPI: 1 = softplus(acc + bias[col])
template<int EPI>
__global__ void __launch_bounds__(256) sgemm128(const float* __restrict__ A,
                                                const float* __restrict__ B,
                                                float* __restrict__ C,
                                                int M, int N, int K,
                                                int lda, int ldb, int ldc,
                                                const float* __restrict__ bias)
{
    __shared__ float As[8][128];
    __shared__ float Bs[8][128];
    const int tid = threadIdx.x;
    const int bm = blockIdx.y*128, bn = blockIdx.x*128;
    const int ty = tid>>4, tx = tid&15;
    const int arow = tid>>1,  acol = (tid&1)*4;
    const int brow = tid>>5,  bcol = (tid&31)*4;

    const float* Ap = A + (size_t)(bm+arow)*lda + acol;
    const float* Bp = B + (size_t)brow*ldb + bn + bcol;

    float4 af = *(const float4*)Ap;
    float4 bf = *(const float4*)Bp;

    float acc[8][8];
    #pragma unroll
    for (int i=0;i<8;i++)
        #pragma unroll
        for (int j=0;j<8;j++) acc[i][j]=0.f;

    for (int k0=0; k0<K; k0+=8){
        As[acol+0][arow]=af.x; As[acol+1][arow]=af.y;
        As[acol+2][arow]=af.z; As[acol+3][arow]=af.w;
        *(float4*)&Bs[brow][bcol] = bf;
        __syncthreads();
        if (k0+8 < K){
            af = *(const float4*)(Ap + (k0+8));
            bf = *(const float4*)(Bp + (size_t)(k0+8)*ldb);
        }
        #pragma unroll
        for (int k=0;k<8;k++){
            float ar[8], br[8];
            *(float4*)&ar[0] = *(const float4*)&As[k][ty*8];
            *(float4*)&ar[4] = *(const float4*)&As[k][ty*8+4];
            *(float4*)&br[0] = *(const float4*)&Bs[k][tx*8];
            *(float4*)&br[4] = *(const float4*)&Bs[k][tx*8+4];
            #pragma unroll
            for (int i=0;i<8;i++)
                #pragma unroll
                for (int j=0;j<8;j++)
                    acc[i][j] = fmaf(ar[i], br[j], acc[i][j]);
        }
        __syncthreads();
    }

    #pragma unroll
    for (int i=0;i<8;i++){
        int r = bm + ty*8 + i;
        float vals[8];
        #pragma unroll
        for (int j=0;j<8;j++){
            float v = acc[i][j];
            int c = bn + tx*8 + j;
            if (EPI==1) v = softplus_f(v + bias[c]);
            vals[j] = v;
        }
        float* cp = C + (size_t)r*ldc + bn + tx*8;
        *(float4*)cp     = *(float4*)&vals[0];
        *(float4*)(cp+4) = *(float4*)&vals[4];
    }
}

// ---------------- depthwise causal conv (width 4) + SiLU -----------------
__global__ void __launch_bounds__(256) conv_silu_kernel(const float* __restrict__ xz,
                                                        const float* __restrict__ cw,
                                                        const float* __restrict__ cb,
                                                        float* __restrict__ u)
{
    int lin = blockIdx.x*256 + threadIdx.x;        // over NTOK * DINNER/4
    int d4  = lin & (DINNER/4 - 1);
    int tok = lin >> 9;                            // DINNER/4 = 512
    int t   = tok & (SEQ-1);
    int d   = d4*4;

    float4 acc = *(const float4*)(cb + d);
    float w0[4], w1[4], w2[4], w3[4];
    *(float4*)w0 = *(const float4*)(cw + (size_t)(d+0)*4);
    *(float4*)w1 = *(const float4*)(cw + (size_t)(d+1)*4);
    *(float4*)w2 = *(const float4*)(cw + (size_t)(d+2)*4);
    *(float4*)w3 = *(const float4*)(cw + (size_t)(d+3)*4);

    const float* base = xz + (size_t)tok*(2*DINNER) + d;
    #pragma unroll
    for (int j=0;j<4;j++){
        int tt = t - 3 + j;
        if (tt >= 0){
            float4 xv = *(const float4*)(base + (ptrdiff_t)(j-3)*(2*DINNER));
            acc.x = fmaf(xv.x, w0[j], acc.x);
            acc.y = fmaf(xv.y, w1[j], acc.y);
            acc.z = fmaf(xv.z, w2[j], acc.z);
            acc.w = fmaf(xv.w, w3[j], acc.w);
        }
    }
    float4 o;
    o.x = silu_f(acc.x); o.y = silu_f(acc.y);
    o.z = silu_f(acc.z); o.w = silu_f(acc.w);
    *(float4*)(u + (size_t)tok*DINNER + d) = o;
}

// ---------------- skinny GEMM: x_dbl = u @ W_x  (4096 x 96 x 2048) -------
// M-tile 32 -> grid 128 blocks (better SM coverage than 64)
__global__ void __launch_bounds__(256) gemm_xdbl_kernel(const float* __restrict__ A,
                                                        const float* __restrict__ B,
                                                        float* __restrict__ C)
{
    __shared__ float As[32][36];
    __shared__ float Bs[32][100];
    int tid = threadIdx.x;
    int bm  = blockIdx.x*32;
    int ty  = tid>>4, tx = tid&15;
    float acc[2][6];
    #pragma unroll
    for (int i=0;i<2;i++)
        #pragma unroll
        for (int j=0;j<6;j++) acc[i][j]=0.f;

    for (int k0=0;k0<DINNER;k0+=32){
        {
            int m = tid>>3, k4 = (tid&7)*4;
            float4 v = *(const float4*)(A + (size_t)(bm+m)*DINNER + k0 + k4);
            As[k4+0][m]=v.x; As[k4+1][m]=v.y; As[k4+2][m]=v.z; As[k4+3][m]=v.w;
        }
        #pragma unroll
        for (int i=0;i<3;i++){
            int lin = tid + i*256;
            int kr = lin/24, c4 = (lin%24)*4;
            float4 v = *(const float4*)(B + (size_t)(k0+kr)*XDN + c4);
            *(float4*)&Bs[kr][c4] = v;
        }
        __syncthreads();
        #pragma unroll
        for (int k=0;k<32;k++){
            float a[2], bb[6];
            #pragma unroll
            for (int i=0;i<2;i++) a[i]=As[k][ty*2+i];
            #pragma unroll
            for (int j=0;j<6;j++) bb[j]=Bs[k][tx*6+j];
            #pragma unroll
            for (int i=0;i<2;i++)
                #pragma unroll
                for (int j=0;j<6;j++)
                    acc[i][j] = fmaf(a[i], bb[j], acc[i][j]);
        }
        __syncthreads();
    }
    #pragma unroll
    for (int i=0;i<2;i++)
        #pragma unroll
        for (int j=0;j<6;j++)
            C[(size_t)(bm+ty*2+i)*XDN + tx*6 + j] = acc[i][j];
}

// ---------------- selective scan (fused gating output) -------------------
__global__ void __launch_bounds__(256) scan_kernel(const float* __restrict__ delta,
                                                   const float* __restrict__ u,
                                                   const float* __restrict__ xdbl,
                                                   const float* __restrict__ xz,
                                                   const float* __restrict__ A_log,
                                                   const float* __restrict__ D_skip,
                                                   float* __restrict__ y)
{
    int b    = blockIdx.y;
    int tid  = threadIdx.x;
    int warp = tid>>5;
    int lane = tid&31;
    int half = lane>>4;
    int s    = lane&15;
    int d    = blockIdx.x*16 + warp*2 + half;

    float Aval = -expf(A_log[(size_t)d*DSTATE + s]);
    float Dv   = D_skip[d];

    const float* drow = delta + (size_t)b*SEQ*DINNER + d;
    const float* urow = u     + (size_t)b*SEQ*DINNER + d;
    const float* zrow = xz    + (size_t)b*SEQ*(2*DINNER) + DINNER + d;
    const float* xb   = xdbl  + (size_t)b*SEQ*XDN + DTRANK + s;
    float*       yrow = y     + (size_t)b*SEQ*DINNER + d;

    float h = 0.f;
    for (int t=0; t<SEQ; t++){
        float dlt = __ldg(drow + (size_t)t*DINNER);
        float uu  = __ldg(urow + (size_t)t*DINNER);
        float Bv  = __ldg(xb + (size_t)t*XDN);
        float Cv  = __ldg(xb + (size_t)t*XDN + DSTATE);
        float dA  = __expf(dlt * Aval);
        h = fmaf(dA, h, (dlt*uu)*Bv);
        float yp = h * Cv;
        yp += __shfl_xor_sync(0xffffffffu, yp, 1);
        yp += __shfl_xor_sync(0xffffffffu, yp, 2);
        yp += __shfl_xor_sync(0xffffffffu, yp, 4);
        yp += __shfl_xor_sync(0xffffffffu, yp, 8);
        if (s == 0){
            float zz = __ldg(zrow + (size_t)t*(2*DINNER));
            yrow[(size_t)t*DINNER] = (yp + uu*Dv) * silu_f(zz);
        }
    }
}

// ---------------- launch ----------------
extern "C" void kernel_launch(void* const* d_in, const int* in_sizes, int n_in,
                              void* d_out, int out_size)
{
    const float* x      = (const float*)d_in[0];
    const float* ln_w   = (const float*)d_in[1];
    const float* ln_b   = (const float*)d_in[2];
    const float* W_in   = (const float*)d_in[3];
    const float* conv_w = (const float*)d_in[4];
    const float* conv_b = (const float*)d_in[5];
    const float* W_x    = (const float*)d_in[6];
    const float* W_dt   = (const float*)d_in[7];
    const float* b_dt   = (const float*)d_in[8];
    const float* A_log  = (const float*)d_in[9];
    const float* D_skip = (const float*)d_in[10];
    const float* W_out  = (const float*)d_in[11];
    float* out = (float*)d_out;

    float *xn, *xz, *u, *xdbl, *delta, *y;
    cudaGetSymbolAddress((void**)&xn,    g_xn);
    cudaGetSymbolAddress((void**)&xz,    g_xz);
    cudaGetSymbolAddress((void**)&u,     g_u);
    cudaGetSymbolAddress((void**)&xdbl,  g_xdbl);
    cudaGetSymbolAddress((void**)&delta, g_delta);
    cudaGetSymbolAddress((void**)&y,     g_y);

    // 1) LayerNorm
    ln_kernel<<<NTOK, 256>>>(x, ln_w, ln_b, xn);

    // 2) xz = xn @ W_in   [4096 x 4096 x 1024]  (tf32 tensor cores)
    tf32gemm<0><<<dim3((2*DINNER)/128, NTOK/128), 256>>>(
        xn, W_in, xz, NTOK, 2*DINNER, DMODEL, DMODEL, 2*DINNER, 2*DINNER,
        nullptr, 0);

    // 3) depthwise causal conv + silu -> u
    conv_silu_kernel<<<(NTOK*(DINNER/4))/256, 256>>>(xz, conv_w, conv_b, u);

    // 4) x_dbl = u @ W_x  [4096 x 96 x 2048]
    gemm_xdbl_kernel<<<NTOK/32, 256>>>(u, W_x, xdbl);

    // 5) delta = softplus(dt @ W_dt + b_dt)  [4096 x 2048 x 64] (exact fp32)
    sgemm128<1><<<dim3(DINNER/128, NTOK/128), 256>>>(
        xdbl, W_dt, delta, NTOK, DINNER, DTRANK, XDN, DINNER, DINNER, b_dt);

    // 6) selective scan + gating -> y
    scan_kernel<<<dim3(DINNER/16, BATCH), 256>>>(delta, u, xdbl, xz, A_log, D_skip, y);

    // 7) out = gelu(y @ W_out) + x  [4096 x 1024 x 2048]  (tf32 tensor cores)
    tf32gemm<2><<<dim3(DMODEL/128, NTOK/128), 256>>>(
        y, W_out, out, NTOK, DMODEL, DINNER, DINNER, DMODEL, DMODEL,
        x, DMODEL);
}

// round 4
// speedup vs baseline: 1.3183x; 1.0110x over previous
#include <cuda_runtime.h>
#include <math.h>

#define BATCH  2
#define SEQ    2048
#define DMODEL 1024
#define DINNER 2048
#define DSTATE 16
#define DTRANK 64
#define NTOK   (BATCH*SEQ)     /* 4096 tokens */
#define XDN    96              /* dt_rank + 2*d_state */

// ---------------- scratch (static device globals; no allocation) ----------
__device__ float g_xn[NTOK*DMODEL];            // 16 MB
__device__ float g_xz[NTOK*2*DINNER];          // 64 MB
__device__ float g_u[NTOK*DINNER];             // 32 MB
__device__ float g_xdbl[NTOK*XDN];             // 1.5 MB
__device__ float g_delta[NTOK*DINNER];         // 32 MB
__device__ float g_y[NTOK*DINNER];             // 32 MB

// ---------------- helpers ----------------
__device__ __forceinline__ float softplus_f(float x){
    return (x > 20.f) ? x : log1pf(expf(x));
}
__device__ __forceinline__ float gelu_f(float x){
    return 0.5f * x * (1.f + erff(x * 0.70710678118654752440f));
}
__device__ __forceinline__ float silu_f(float x){
    return x * (1.f / (1.f + __expf(-x)));
}
__device__ __forceinline__ unsigned f2tf(float x){
    unsigned u; asm("cvt.rna.tf32.f32 %0, %1;" : "=r"(u) : "f"(x)); return u;
}
__device__ __forceinline__ void mma_tf32(float c[4], const unsigned a[4], const unsigned b[2]){
    asm volatile("mma.sync.aligned.m16n8k8.row.col.f32.tf32.tf32.f32 "
        "{%0,%1,%2,%3},{%4,%5,%6,%7},{%8,%9},{%0,%1,%2,%3};"
        : "+f"(c[0]), "+f"(c[1]), "+f"(c[2]), "+f"(c[3])
        : "r"(a[0]), "r"(a[1]), "r"(a[2]), "r"(a[3]), "r"(b[0]), "r"(b[1]));
}
__device__ __forceinline__ void cp16(float* smem, const float* g){
    unsigned saddr = (unsigned)__cvta_generic_to_shared(smem);
    asm volatile("cp.async.cg.shared.global [%0], [%1], 16;\n" :: "r"(saddr), "l"(g));
}
__device__ __forceinline__ void cp_commit(){ asm volatile("cp.async.commit_group;\n"); }
__device__ __forceinline__ void cp_wait1(){ asm volatile("cp.async.wait_group 1;\n"); }

// ---------------- LayerNorm: one block per token ----------------
__global__ void __launch_bounds__(256) ln_kernel(const float* __restrict__ x,
                                                 const float* __restrict__ w,
                                                 const float* __restrict__ b,
                                                 float* __restrict__ out)
{
    int row = blockIdx.x;
    int tid = threadIdx.x;
    const float4* xr = reinterpret_cast<const float4*>(x + (size_t)row*DMODEL);
    float4 v = xr[tid];
    float s = v.x+v.y+v.z+v.w;
    float q = v.x*v.x+v.y*v.y+v.z*v.z+v.w*v.w;
    #pragma unroll
    for (int o=16;o>0;o>>=1){
        s += __shfl_down_sync(0xffffffffu, s, o);
        q += __shfl_down_sync(0xffffffffu, q, o);
    }
    __shared__ float ss[8], sq[8];
    __shared__ float mu_s, inv_s;
    int wp = tid>>5, ln = tid&31;
    if (ln==0){ ss[wp]=s; sq[wp]=q; }
    __syncthreads();
    if (tid==0){
        float ts=0.f, tq=0.f;
        #pragma unroll
        for (int i=0;i<8;i++){ ts+=ss[i]; tq+=sq[i]; }
        float mu  = ts * (1.f/DMODEL);
        float var = tq * (1.f/DMODEL) - mu*mu;
        mu_s = mu; inv_s = rsqrtf(var + 1e-5f);
    }
    __syncthreads();
    float mu = mu_s, inv = inv_s;
    float4 wv = reinterpret_cast<const float4*>(w)[tid];
    float4 bv = reinterpret_cast<const float4*>(b)[tid];
    float4 o;
    o.x = (v.x-mu)*inv*wv.x + bv.x;
    o.y = (v.y-mu)*inv*wv.y + bv.y;
    o.z = (v.z-mu)*inv*wv.z + bv.z;
    o.w = (v.w-mu)*inv*wv.w + bv.w;
    reinterpret_cast<float4*>(out + (size_t)row*DMODEL)[tid] = o;
}

// ================== TF32 tensor-core GEMM 128x128, 8 warps ================
// C[M,N] = A[M,K] @ B[K,N], row-major. M,N mult of 128, K mult of 16.
// EPI: 0 = plain, 2 = gelu(acc) + res[row,col]
#define AS_LD 20
#define BS_LD 136

template<int EPI>
__global__ void __launch_bounds__(256,2) tf32gemm(const float* __restrict__ A,
                                                  const float* __restrict__ B,
                                                  float* __restrict__ C,
                                                  int M, int N, int K,
                                                  int lda, int ldb, int ldc,
                                                  const float* __restrict__ res,
                                                  int ldres)
{
    __shared__ float As[2][128*AS_LD];
    __shared__ float Bs[2][16*BS_LD];

    const int tid  = threadIdx.x;
    const int warp = tid>>5, lane = tid&31;
    const int wm = warp>>2, wn = warp&3;        // 2 x 4 warp grid
    const int g  = lane>>2, tg = lane&3;
    const int bm = blockIdx.y*128, bn = blockIdx.x*128;

    // staging indices (2 chunks of 16B per thread per tile)
    const float* aptr[2]; int asm_[2];
    const float* bptr[2]; int bsm_[2];
    #pragma unroll
    for (int s=0;s<2;s++){
        int c  = tid + s*256;
        int m  = c>>2, k4 = (c&3)*4;
        aptr[s] = A + (size_t)(bm+m)*lda + k4;
        asm_[s] = m*AS_LD + k4;
        int kr = c>>5, n4 = (c&31)*4;
        bptr[s] = B + (size_t)kr*ldb + bn + n4;
        bsm_[s] = kr*BS_LD + n4;
    }

    float acc[4][4][4];
    #pragma unroll
    for (int i=0;i<4;i++)
        #pragma unroll
        for (int j=0;j<4;j++)
            #pragma unroll
            for (int r=0;r<4;r++) acc[i][j][r]=0.f;

    const int nkt = K/16;
    // prologue: stages 0 and 1
    #pragma unroll
    for (int st=0; st<2; st++){
        int k0 = st*16;
        #pragma unroll
        for (int s=0;s<2;s++){
            cp16(&As[st][asm_[s]], aptr[s] + k0);
            cp16(&Bs[st][bsm_[s]], bptr[s] + (size_t)k0*ldb);
        }
        cp_commit();
    }

    for (int kt=0; kt<nkt; kt++){
        cp_wait1();
        __syncthreads();
        int buf = kt & 1;
        const float* as = As[buf];
        const float* bs = Bs[buf];
        #pragma unroll
        for (int kg=0; kg<16; kg+=8){
            unsigned af[4][4], bf[4][2];
            #pragma unroll
            for (int i=0;i<4;i++){
                int mr = wm*64 + i*16 + g;
                af[i][0] = f2tf(as[ mr   *AS_LD + kg+tg  ]);
                af[i][1] = f2tf(as[(mr+8)*AS_LD + kg+tg  ]);
                af[i][2] = f2tf(as[ mr   *AS_LD + kg+tg+4]);
                af[i][3] = f2tf(as[(mr+8)*AS_LD + kg+tg+4]);
            }
            #pragma unroll
            for (int j=0;j<4;j++){
                int nc = wn*32 + j*8 + g;
                bf[j][0] = f2tf(bs[(kg+tg  )*BS_LD + nc]);
                bf[j][1] = f2tf(bs[(kg+tg+4)*BS_LD + nc]);
            }
            #pragma unroll
            for (int i=0;i<4;i++)
                #pragma unroll
                for (int j=0;j<4;j++)
                    mma_tf32(acc[i][j], af[i], bf[j]);
        }
        __syncthreads();
        if (kt+2 < nkt){
            int k0 = (kt+2)*16;
            #pragma unroll
            for (int s=0;s<2;s++){
                cp16(&As[buf][asm_[s]], aptr[s] + k0);
                cp16(&Bs[buf][bsm_[s]], bptr[s] + (size_t)k0*ldb);
            }
        }
        cp_commit();
    }

    // epilogue
    #pragma unroll
    for (int i=0;i<4;i++){
        #pragma unroll
        for (int j=0;j<4;j++){
            int r = bm + wm*64 + i*16 + g;
            int c = bn + wn*32 + j*8 + tg*2;
            float v0=acc[i][j][0], v1=acc[i][j][1];
            float v2=acc[i][j][2], v3=acc[i][j][3];
            if (EPI==2){
                v0 = gelu_f(v0) + res[(size_t)r*ldres + c];
                v1 = gelu_f(v1) + res[(size_t)r*ldres + c + 1];
                v2 = gelu_f(v2) + res[(size_t)(r+8)*ldres + c];
                v3 = gelu_f(v3) + res[(size_t)(r+8)*ldres + c + 1];
            }
            float2 p0 = make_float2(v0,v1);
            float2 p1 = make_float2(v2,v3);
            *(float2*)(C + (size_t)r*ldc + c)     = p0;
            *(float2*)(C + (size_t)(r+8)*ldc + c) = p1;
        }
    }
}

// ---------------- SGEMM 128x128x8 fp32 (kept for the delta GEMM) ---------
// EPI: 1 = softplus(acc + bias[col])
template<int EPI>
__global__ void __launch_bounds__(256) sgemm128(const float* __restrict__ A,
                                                const float* __restrict__ B,
                                                float* __restrict__ C,
                                                int M, int N, int K,
                                                int lda, int ldb, int ldc,
                                                const float* __restrict__ bias)
{
    __shared__ float As[8][128];
    __shared__ float Bs[8][128];
    const int tid = threadIdx.x;
    const int bm = blockIdx.y*128, bn = blockIdx.x*128;
    const int ty = tid>>4, tx = tid&15;
    const int arow = tid>>1,  acol = (tid&1)*4;
    const int brow = tid>>5,  bcol = (tid&31)*4;

    const float* Ap = A + (size_t)(bm+arow)*lda + acol;
    const float* Bp = B + (size_t)brow*ldb + bn + bcol;

    float4 af = *(const float4*)Ap;
    float4 bf = *(const float4*)Bp;

    float acc[8][8];
    #pragma unroll
    for (int i=0;i<8;i++)
        #pragma unroll
        for (int j=0;j<8;j++) acc[i][j]=0.f;

    for (int k0=0; k0<K; k0+=8){
        As[acol+0][arow]=af.x; As[acol+1][arow]=af.y;
        As[acol+2][arow]=af.z; As[acol+3][arow]=af.w;
        *(float4*)&Bs[brow][bcol] = bf;
        __syncthreads();
        if (k0+8 < K){
            af = *(const float4*)(Ap + (k0+8));
            bf = *(const float4*)(Bp + (size_t)(k0+8)*ldb);
        }
        #pragma unroll
        for (int k=0;k<8;k++){
            float ar[8], br[8];
            *(float4*)&ar[0] = *(const float4*)&As[k][ty*8];
            *(float4*)&ar[4] = *(const float4*)&As[k][ty*8+4];
            *(float4*)&br[0] = *(const float4*)&Bs[k][tx*8];
            *(float4*)&br[4] = *(const float4*)&Bs[k][tx*8+4];
            #pragma unroll
            for (int i=0;i<8;i++)
                #pragma unroll
                for (int j=0;j<8;j++)
                    acc[i][j] = fmaf(ar[i], br[j], acc[i][j]);
        }
        __syncthreads();
    }

    #pragma unroll
    for (int i=0;i<8;i++){
        int r = bm + ty*8 + i;
        float vals[8];
        #pragma unroll
        for (int j=0;j<8;j++){
            float v = acc[i][j];
            int c = bn + tx*8 + j;
            if (EPI==1) v = softplus_f(v + bias[c]);
            vals[j] = v;
        }
        float* cp = C + (size_t)r*ldc + bn + tx*8;
        *(float4*)cp     = *(float4*)&vals[0];
        *(float4*)(cp+4) = *(float4*)&vals[4];
    }
}

// ---------------- depthwise causal conv (width 4) + SiLU -----------------
__global__ void __launch_bounds__(256) conv_silu_kernel(const float* __restrict__ xz,
                                                        const float* __restrict__ cw,
                                                        const float* __restrict__ cb,
                                                        float* __restrict__ u)
{
    int lin = blockIdx.x*256 + threadIdx.x;        // over NTOK * DINNER/4
    int d4  = lin & (DINNER/4 - 1);
    int tok = lin >> 9;                            // DINNER/4 = 512
    int t   = tok & (SEQ-1);
    int d   = d4*4;

    float4 acc = *(const float4*)(cb + d);
    float w0[4], w1[4], w2[4], w3[4];
    *(float4*)w0 = *(const float4*)(cw + (size_t)(d+0)*4);
    *(float4*)w1 = *(const float4*)(cw + (size_t)(d+1)*4);
    *(float4*)w2 = *(const float4*)(cw + (size_t)(d+2)*4);
    *(float4*)w3 = *(const float4*)(cw + (size_t)(d+3)*4);

    const float* base = xz + (size_t)tok*(2*DINNER) + d;
    #pragma unroll
    for (int j=0;j<4;j++){
        int tt = t - 3 + j;
        if (tt >= 0){
            float4 xv = *(const float4*)(base + (ptrdiff_t)(j-3)*(2*DINNER));
            acc.x = fmaf(xv.x, w0[j], acc.x);
            acc.y = fmaf(xv.y, w1[j], acc.y);
            acc.z = fmaf(xv.z, w2[j], acc.z);
            acc.w = fmaf(xv.w, w3[j], acc.w);
        }
    }
    float4 o;
    o.x = silu_f(acc.x); o.y = silu_f(acc.y);
    o.z = silu_f(acc.z); o.w = silu_f(acc.w);
    *(float4*)(u + (size_t)tok*DINNER + d) = o;
}

// ---------------- skinny GEMM: x_dbl = u @ W_x  (4096 x 96 x 2048) -------
// M-tile 32 -> grid 128 blocks (better SM coverage than 64)
__global__ void __launch_bounds__(256) gemm_xdbl_kernel(const float* __restrict__ A,
                                                        const float* __restrict__ B,
                                                        float* __restrict__ C)
{
    __shared__ float As[32][36];
    __shared__ float Bs[32][100];
    int tid = threadIdx.x;
    int bm  = blockIdx.x*32;
    int ty  = tid>>4, tx = tid&15;
    float acc[2][6];
    #pragma unroll
    for (int i=0;i<2;i++)
        #pragma unroll
        for (int j=0;j<6;j++) acc[i][j]=0.f;

    for (int k0=0;k0<DINNER;k0+=32){
        {
            int m = tid>>3, k4 = (tid&7)*4;
            float4 v = *(const float4*)(A + (size_t)(bm+m)*DINNER + k0 + k4);
            As[k4+0][m]=v.x; As[k4+1][m]=v.y; As[k4+2][m]=v.z; As[k4+3][m]=v.w;
        }
        #pragma unroll
        for (int i=0;i<3;i++){
            int lin = tid + i*256;
            int kr = lin/24, c4 = (lin%24)*4;
            float4 v = *(const float4*)(B + (size_t)(k0+kr)*XDN + c4);
            *(float4*)&Bs[kr][c4] = v;
        }
        __syncthreads();
        #pragma unroll
        for (int k=0;k<32;k++){
            float a[2], bb[6];
            #pragma unroll
            for (int i=0;i<2;i++) a[i]=As[k][ty*2+i];
            #pragma unroll
            for (int j=0;j<6;j++) bb[j]=Bs[k][tx*6+j];
            #pragma unroll
            for (int i=0;i<2;i++)
                #pragma unroll
                for (int j=0;j<6;j++)
                    acc[i][j] = fmaf(a[i], bb[j], acc[i][j]);
        }
        __syncthreads();
    }
    #pragma unroll
    for (int i=0;i<2;i++)
        #pragma unroll
        for (int j=0;j<6;j++)
            C[(size_t)(bm+ty*2+i)*XDN + tx*6 + j] = acc[i][j];
}

// ---------------- selective scan (fused gating output) -------------------
__global__ void __launch_bounds__(256) scan_kernel(const float* __restrict__ delta,
                                                   const float* __restrict__ u,
                                                   const float* __restrict__ xdbl,
                                                   const float* __restrict__ xz,
                                                   const float* __restrict__ A_log,
                                                   const float* __restrict__ D_skip,
                                                   float* __restrict__ y)
{
    int b    = blockIdx.y;
    int tid  = threadIdx.x;
    int warp = tid>>5;
    int lane = tid&31;
    int half = lane>>4;
    int s    = lane&15;
    int d    = blockIdx.x*16 + warp*2 + half;

    float Aval = -expf(A_log[(size_t)d*DSTATE + s]);
    float Dv   = D_skip[d];

    const float* drow = delta + (size_t)b*SEQ*DINNER + d;
    const float* urow = u     + (size_t)b*SEQ*DINNER + d;
    const float* zrow = xz    + (size_t)b*SEQ*(2*DINNER) + DINNER + d;
    const float* xb   = xdbl  + (size_t)b*SEQ*XDN + DTRANK + s;
    float*       yrow = y     + (size_t)b*SEQ*DINNER + d;

    float h = 0.f;
    for (int t=0; t<SEQ; t++){
        float dlt = __ldg(drow + (size_t)t*DINNER);
        float uu  = __ldg(urow + (size_t)t*DINNER);
        float Bv  = __ldg(xb + (size_t)t*XDN);
        float Cv  = __ldg(xb + (size_t)t*XDN + DSTATE);
        float dA  = __expf(dlt * Aval);
        h = fmaf(dA, h, (dlt*uu)*Bv);
        float yp = h * Cv;
        yp += __shfl_xor_sync(0xffffffffu, yp, 1);
        yp += __shfl_xor_sync(0xffffffffu, yp, 2);
        yp += __shfl_xor_sync(0xffffffffu, yp, 4);
        yp += __shfl_xor_sync(0xffffffffu, yp, 8);
        if (s == 0){
            float zz = __ldg(zrow + (size_t)t*(2*DINNER));
            yrow[(size_t)t*DINNER] = (yp + uu*Dv) * silu_f(zz);
        }
    }
}

// ---------------- launch ----------------
extern "C" void kernel_launch(void* const* d_in, const int* in_sizes, int n_in,
                              void* d_out, int out_size)
{
    const float* x      = (const float*)d_in[0];
    const float* ln_w   = (const float*)d_in[1];
    const float* ln_b   = (const float*)d_in[2];
    const float* W_in   = (const float*)d_in[3];
    const float* conv_w = (const float*)d_in[4];
    const float* conv_b = (const float*)d_in[5];
    const float* W_x    = (const float*)d_in[6];
    const float* W_dt   = (const float*)d_in[7];
    const float* b_dt   = (const float*)d_in[8];
    const float* A_log  = (const float*)d_in[9];
    const float* D_skip = (const float*)d_in[10];
    const float* W_out  = (const float*)d_in[11];
    float* out = (float*)d_out;

    float *xn, *xz, *u, *xdbl, *delta, *y;
    cudaGetSymbolAddress((void**)&xn,    g_xn);
    cudaGetSymbolAddress((void**)&xz,    g_xz);
    cudaGetSymbolAddress((void**)&u,     g_u);
    cudaGetSymbolAddress((void**)&xdbl,  g_xdbl);
    cudaGetSymbolAddress((void**)&delta, g_delta);
    cudaGetSymbolAddress((void**)&y,     g_y);

    // 1) LayerNorm
    ln_kernel<<<NTOK, 256>>>(x, ln_w, ln_b, xn);

    // 2) xz = xn @ W_in   [4096 x 4096 x 1024]  (tf32 tensor cores)
    tf32gemm<0><<<dim3((2*DINNER)/128, NTOK/128), 256>>>(
        xn, W_in, xz, NTOK, 2*DINNER, DMODEL, DMODEL, 2*DINNER, 2*DINNER,
        nullptr, 0);

    // 3) depthwise causal conv + silu -> u
    conv_silu_kernel<<<(NTOK*(DINNER/4))/256, 256>>>(xz, conv_w, conv_b, u);

    // 4) x_dbl = u @ W_x  [4096 x 96 x 2048]
    gemm_xdbl_kernel<<<NTOK/32, 256>>>(u, W_x, xdbl);

    // 5) delta = softplus(dt @ W_dt + b_dt)  [4096 x 2048 x 64] (exact fp32)
    sgemm128<1><<<dim3(DINNER/128, NTOK/128), 256>>>(
        xdbl, W_dt, delta, NTOK, DINNER, DTRANK, XDN, DINNER, DINNER, b_dt);

    // 6) selective scan + gating -> y
    scan_kernel<<<dim3(DINNER/16, BATCH), 256>>>(delta, u, xdbl, xz, A_log, D_skip, y);

    // 7) out = gelu(y @ W_out) + x  [4096 x 1024 x 2048]  (tf32 tensor cores)
    tf32gemm<2><<<dim3(DMODEL/128, NTOK/128), 256>>>(
        y, W_out, out, NTOK, DMODEL, DINNER, DINNER, DMODEL, DMODEL,
        x, DMODEL);
}

// round 8
// speedup vs baseline: 3.3958x; 2.5758x over previous
#include <cuda_runtime.h>
#include <cstdint>
#include <math.h>

#define BATCH  2
#define SEQ    2048
#define DMODEL 1024
#define DINNER 2048
#define DSTATE 16
#define DTRANK 64
#define NTOK   (BATCH*SEQ)
#define XDN    96

// ---------------- scratch (static device globals; no allocation) ----------
__device__ float g_xn[NTOK*DMODEL];            // tf32-rounded
__device__ float g_xz[NTOK*2*DINNER];
__device__ float g_u[NTOK*DINNER];
__device__ float g_xpart[4*NTOK*XDN];
__device__ float g_xdbl[NTOK*XDN];
__device__ float g_delta[NTOK*DINNER];
__device__ float g_y[NTOK*DINNER];             // tf32-rounded
__device__ float g_Wi[DMODEL*2*DINNER];        // tf32-rounded W_in
__device__ float g_Wo[DINNER*DMODEL];          // tf32-rounded W_out

// ---------------- helpers ----------------
__device__ __forceinline__ float softplus_f(float x){
    return (x > 20.f) ? x : log1pf(expf(x));
}
__device__ __forceinline__ float gelu_f(float x){
    return 0.5f * x * (1.f + erff(x * 0.70710678118654752440f));
}
__device__ __forceinline__ float silu_f(float x){
    return x * (1.f / (1.f + __expf(-x)));
}
__device__ __forceinline__ float f2tf_f(float x){
    unsigned u; asm("cvt.rna.tf32.f32 %0, %1;" : "=r"(u) : "f"(x));
    return __uint_as_float(u);
}
__device__ __forceinline__ void mma_tf32(float c[4], const unsigned a[4], const unsigned b[2]){
    asm volatile("mma.sync.aligned.m16n8k8.row.col.f32.tf32.tf32.f32 "
        "{%0,%1,%2,%3},{%4,%5,%6,%7},{%8,%9},{%0,%1,%2,%3};"
        : "+f"(c[0]), "+f"(c[1]), "+f"(c[2]), "+f"(c[3])
        : "r"(a[0]), "r"(a[1]), "r"(a[2]), "r"(a[3]), "r"(b[0]), "r"(b[1]));
}
__device__ __forceinline__ void cp16(void* smem, const void* g){
    unsigned saddr = (unsigned)__cvta_generic_to_shared(smem);
    asm volatile("cp.async.cg.shared.global [%0], [%1], 16;\n" :: "r"(saddr), "l"(g));
}
__device__ __forceinline__ void cp_commit(){ asm volatile("cp.async.commit_group;\n"); }

// ---------------- weight tf32 pre-round ----------------
__global__ void __launch_bounds__(256) round_tf32(const float* __restrict__ in,
                                                  float* __restrict__ out, int n)
{
    int i = (blockIdx.x*256 + threadIdx.x)*4;
    if (i < n){
        float4 v = *(const float4*)(in + i);
        v.x = f2tf_f(v.x); v.y = f2tf_f(v.y);
        v.z = f2tf_f(v.z); v.w = f2tf_f(v.w);
        *(float4*)(out + i) = v;
    }
}

// ---------------- LayerNorm (tf32-rounded out) ----------------
__global__ void __launch_bounds__(256) ln_kernel(const float* __restrict__ x,
                                                 const float* __restrict__ w,
                                                 const float* __restrict__ b,
                                                 float* __restrict__ out)
{
    int row = blockIdx.x;
    int tid = threadIdx.x;
    const float4* xr = reinterpret_cast<const float4*>(x + (size_t)row*DMODEL);
    float4 v = xr[tid];
    float s = v.x+v.y+v.z+v.w;
    float q = v.x*v.x+v.y*v.y+v.z*v.z+v.w*v.w;
    #pragma unroll
    for (int o=16;o>0;o>>=1){
        s += __shfl_down_sync(0xffffffffu, s, o);
        q += __shfl_down_sync(0xffffffffu, q, o);
    }
    __shared__ float ss[8], sq[8];
    __shared__ float mu_s, inv_s;
    int wp = tid>>5, ln = tid&31;
    if (ln==0){ ss[wp]=s; sq[wp]=q; }
    __syncthreads();
    if (tid==0){
        float ts=0.f, tq=0.f;
        #pragma unroll
        for (int i=0;i<8;i++){ ts+=ss[i]; tq+=sq[i]; }
        float mu  = ts * (1.f/DMODEL);
        float var = tq * (1.f/DMODEL) - mu*mu;
        mu_s = mu; inv_s = rsqrtf(var + 1e-5f);
    }
    __syncthreads();
    float mu = mu_s, inv = inv_s;
    float4 wv = reinterpret_cast<const float4*>(w)[tid];
    float4 bv = reinterpret_cast<const float4*>(b)[tid];
    float4 o;
    o.x = f2tf_f((v.x-mu)*inv*wv.x + bv.x);
    o.y = f2tf_f((v.y-mu)*inv*wv.y + bv.y);
    o.z = f2tf_f((v.z-mu)*inv*wv.z + bv.z);
    o.w = f2tf_f((v.w-mu)*inv*wv.w + bv.w);
    reinterpret_cast<float4*>(out + (size_t)row*DMODEL)[tid] = o;
}

// ======== TF32 GEMM v2: 128x128, 8 warps, 3-stage cp.async, no in-loop cvt
// C[M,N] = A[M,K] @ B[K,N], row-major, operands pre-rounded to tf32.
// EPI: 0 plain, 2 gelu(acc)+res
#define AS_LD 20
#define BS_LD 136
#define ASTG  (128*AS_LD)     /* floats per A stage: 2560 */
#define BSTG  (16*BS_LD)      /* floats per B stage: 2176 */
#define GSMEM ((3*(ASTG+BSTG))*4)   /* 56832 bytes */

template<int EPI>
__global__ void __launch_bounds__(256,2) tf32gemm(const float* __restrict__ A,
                                                  const float* __restrict__ B,
                                                  float* __restrict__ C,
                                                  int K, int lda, int ldb, int ldc,
                                                  const float* __restrict__ res,
                                                  int ldres)
{
    extern __shared__ float smem[];
    float* As = smem;                 // 3 stages
    float* Bs = smem + 3*ASTG;        // 3 stages

    const int tid  = threadIdx.x;
    const int warp = tid>>5, lane = tid&31;
    const int wm = warp>>2, wn = warp&3;
    const int g  = lane>>2, tg = lane&3;
    const int bm = blockIdx.y*128, bn = blockIdx.x*128;

    const float* aptr[2]; int asm_[2];
    const float* bptr[2]; int bsm_[2];
    #pragma unroll
    for (int s=0;s<2;s++){
        int c  = tid + s*256;
        int m  = c>>2, k4 = (c&3)*4;
        aptr[s] = A + (size_t)(bm+m)*lda + k4;
        asm_[s] = m*AS_LD + k4;
        int kr = c>>5, n4 = (c&31)*4;
        bptr[s] = B + (size_t)kr*ldb + bn + n4;
        bsm_[s] = kr*BS_LD + n4;
    }

    float acc[4][4][4];
    #pragma unroll
    for (int i=0;i<4;i++)
        #pragma unroll
        for (int j=0;j<4;j++)
            #pragma unroll
            for (int r=0;r<4;r++) acc[i][j][r]=0.f;

    const int nkt = K/16;
    // prologue: stages 0,1,2
    #pragma unroll
    for (int st=0; st<3; st++){
        int k0 = st*16;
        #pragma unroll
        for (int s=0;s<2;s++){
            cp16(&As[st*ASTG + asm_[s]], aptr[s] + k0);
            cp16(&Bs[st*BSTG + bsm_[s]], bptr[s] + (size_t)k0*ldb);
        }
        cp_commit();
    }

    int buf = 0;
    for (int kt=0; kt<nkt; kt++){
        asm volatile("cp.async.wait_group 2;\n");
        __syncthreads();
        const float* as = As + buf*ASTG;
        const float* bs = Bs + buf*BSTG;
        #pragma unroll
        for (int kg=0; kg<16; kg+=8){
            unsigned af[4][4], bf[4][2];
            #pragma unroll
            for (int i=0;i<4;i++){
                int mr = wm*64 + i*16 + g;
                af[i][0] = __float_as_uint(as[ mr   *AS_LD + kg+tg  ]);
                af[i][1] = __float_as_uint(as[(mr+8)*AS_LD + kg+tg  ]);
                af[i][2] = __float_as_uint(as[ mr   *AS_LD + kg+tg+4]);
                af[i][3] = __float_as_uint(as[(mr+8)*AS_LD + kg+tg+4]);
            }
            #pragma unroll
            for (int j=0;j<4;j++){
                int nc = wn*32 + j*8 + g;
                bf[j][0] = __float_as_uint(bs[(kg+tg  )*BS_LD + nc]);
                bf[j][1] = __float_as_uint(bs[(kg+tg+4)*BS_LD + nc]);
            }
            #pragma unroll
            for (int i=0;i<4;i++)
                #pragma unroll
                for (int j=0;j<4;j++)
                    mma_tf32(acc[i][j], af[i], bf[j]);
        }
        __syncthreads();
        if (kt+3 < nkt){
            int k0 = (kt+3)*16;
            #pragma unroll
            for (int s=0;s<2;s++){
                cp16(&As[buf*ASTG + asm_[s]], aptr[s] + k0);
                cp16(&Bs[buf*BSTG + bsm_[s]], bptr[s] + (size_t)k0*ldb);
            }
        }
        cp_commit();
        buf = (buf==2) ? 0 : buf+1;
    }

    #pragma unroll
    for (int i=0;i<4;i++){
        #pragma unroll
        for (int j=0;j<4;j++){
            int r = bm + wm*64 + i*16 + g;
            int c = bn + wn*32 + j*8 + tg*2;
            float v0=acc[i][j][0], v1=acc[i][j][1];
            float v2=acc[i][j][2], v3=acc[i][j][3];
            if (EPI==2){
                v0 = gelu_f(v0) + res[(size_t)r*ldres + c];
                v1 = gelu_f(v1) + res[(size_t)r*ldres + c + 1];
                v2 = gelu_f(v2) + res[(size_t)(r+8)*ldres + c];
                v3 = gelu_f(v3) + res[(size_t)(r+8)*ldres + c + 1];
            }
            *(float2*)(C + (size_t)r*ldc + c)     = make_float2(v0,v1);
            *(float2*)(C + (size_t)(r+8)*ldc + c) = make_float2(v2,v3);
        }
    }
}

// ---------------- SGEMM 128x128x8 fp32 (delta GEMM, exact) ---------------
__global__ void __launch_bounds__(256) sgemm_sp(const float* __restrict__ A,
                                                const float* __restrict__ B,
                                                float* __restrict__ C,
                                                int K, int lda, int ldb, int ldc,
                                                const float* __restrict__ bias)
{
    __shared__ float As[8][128];
    __shared__ float Bs[8][128];
    const int tid = threadIdx.x;
    const int bm = blockIdx.y*128, bn = blockIdx.x*128;
    const int ty = tid>>4, tx = tid&15;
    const int arow = tid>>1,  acol = (tid&1)*4;
    const int brow = tid>>5,  bcol = (tid&31)*4;

    const float* Ap = A + (size_t)(bm+arow)*lda + acol;
    const float* Bp = B + (size_t)brow*ldb + bn + bcol;
    float4 af = *(const float4*)Ap;
    float4 bf = *(const float4*)Bp;

    float acc[8][8];
    #pragma unroll
    for (int i=0;i<8;i++)
        #pragma unroll
        for (int j=0;j<8;j++) acc[i][j]=0.f;

    for (int k0=0; k0<K; k0+=8){
        As[acol+0][arow]=af.x; As[acol+1][arow]=af.y;
        As[acol+2][arow]=af.z; As[acol+3][arow]=af.w;
        *(float4*)&Bs[brow][bcol] = bf;
        __syncthreads();
        if (k0+8 < K){
            af = *(const float4*)(Ap + (k0+8));
            bf = *(const float4*)(Bp + (size_t)(k0+8)*ldb);
        }
        #pragma unroll
        for (int k=0;k<8;k++){
            float ar[8], br[8];
            *(float4*)&ar[0] = *(const float4*)&As[k][ty*8];
            *(float4*)&ar[4] = *(const float4*)&As[k][ty*8+4];
            *(float4*)&br[0] = *(const float4*)&Bs[k][tx*8];
            *(float4*)&br[4] = *(const float4*)&Bs[k][tx*8+4];
            #pragma unroll
            for (int i=0;i<8;i++)
                #pragma unroll
                for (int j=0;j<8;j++)
                    acc[i][j] = fmaf(ar[i], br[j], acc[i][j]);
        }
        __syncthreads();
    }
    #pragma unroll
    for (int i=0;i<8;i++){
        int r = bm + ty*8 + i;
        float vals[8];
        #pragma unroll
        for (int j=0;j<8;j++)
            vals[j] = softplus_f(acc[i][j] + bias[bn + tx*8 + j]);
        float* cp_ = C + (size_t)r*ldc + bn + tx*8;
        *(float4*)cp_     = *(float4*)&vals[0];
        *(float4*)(cp_+4) = *(float4*)&vals[4];
    }
}

// ---------------- depthwise causal conv (width 4) + SiLU -----------------
__global__ void __launch_bounds__(256) conv_silu_kernel(const float* __restrict__ xz,
                                                        const float* __restrict__ cw,
                                                        const float* __restrict__ cb,
                                                        float* __restrict__ u)
{
    int lin = blockIdx.x*256 + threadIdx.x;
    int d4  = lin & (DINNER/4 - 1);
    int tok = lin >> 9;
    int t   = tok & (SEQ-1);
    int d   = d4*4;

    float4 acc = *(const float4*)(cb + d);
    float w0[4], w1[4], w2[4], w3[4];
    *(float4*)w0 = *(const float4*)(cw + (size_t)(d+0)*4);
    *(float4*)w1 = *(const float4*)(cw + (size_t)(d+1)*4);
    *(float4*)w2 = *(const float4*)(cw + (size_t)(d+2)*4);
    *(float4*)w3 = *(const float4*)(cw + (size_t)(d+3)*4);

    const float* base = xz + (size_t)tok*(2*DINNER) + d;
    #pragma unroll
    for (int j=0;j<4;j++){
        int tt = t - 3 + j;
        if (tt >= 0){
            float4 xv = *(const float4*)(base + (ptrdiff_t)(j-3)*(2*DINNER));
            acc.x = fmaf(xv.x, w0[j], acc.x);
            acc.y = fmaf(xv.y, w1[j], acc.y);
            acc.z = fmaf(xv.z, w2[j], acc.z);
            acc.w = fmaf(xv.w, w3[j], acc.w);
        }
    }
    float4 o;
    o.x = silu_f(acc.x); o.y = silu_f(acc.y);
    o.z = silu_f(acc.z); o.w = silu_f(acc.w);
    *(float4*)(u + (size_t)tok*DINNER + d) = o;
}

// ---------------- xdbl split-K: partial[kb] = u[:,kb*512:+512] @ W_x -----
__global__ void __launch_bounds__(256) gemm_xdbl_part(const float* __restrict__ A,
                                                      const float* __restrict__ B,
                                                      float* __restrict__ P)
{
    __shared__ float As[32][36];
    __shared__ float Bs[32][100];
    int tid = threadIdx.x;
    int bm  = blockIdx.x*32;
    int kb  = blockIdx.y;
    int ty  = tid>>4, tx = tid&15;
    float acc[2][6];
    #pragma unroll
    for (int i=0;i<2;i++)
        #pragma unroll
        for (int j=0;j<6;j++) acc[i][j]=0.f;

    for (int k0=kb*512; k0<(kb+1)*512; k0+=32){
        {
            int m = tid>>3, k4 = (tid&7)*4;
            float4 v = *(const float4*)(A + (size_t)(bm+m)*DINNER + k0 + k4);
            As[k4+0][m]=v.x; As[k4+1][m]=v.y; As[k4+2][m]=v.z; As[k4+3][m]=v.w;
        }
        #pragma unroll
        for (int i=0;i<3;i++){
            int lin = tid + i*256;
            int kr = lin/24, c4 = (lin%24)*4;
            float4 v = *(const float4*)(B + (size_t)(k0+kr)*XDN + c4);
            *(float4*)&Bs[kr][c4] = v;
        }
        __syncthreads();
        #pragma unroll
        for (int k=0;k<32;k++){
            float a[2], bb[6];
            #pragma unroll
            for (int i=0;i<2;i++) a[i]=As[k][ty*2+i];
            #pragma unroll
            for (int j=0;j<6;j++) bb[j]=Bs[k][tx*6+j];
            #pragma unroll
            for (int i=0;i<2;i++)
                #pragma unroll
                for (int j=0;j<6;j++)
                    acc[i][j] = fmaf(a[i], bb[j], acc[i][j]);
        }
        __syncthreads();
    }
    float* out = P + (size_t)kb*NTOK*XDN;
    #pragma unroll
    for (int i=0;i<2;i++)
        #pragma unroll
        for (int j=0;j<6;j++)
            out[(size_t)(bm+ty*2+i)*XDN + tx*6 + j] = acc[i][j];
}

__global__ void __launch_bounds__(256) xdbl_reduce(const float* __restrict__ P,
                                                   float* __restrict__ C)
{
    int i = blockIdx.x*256 + threadIdx.x;   // over NTOK*XDN
    float v = P[i] + P[i + NTOK*XDN] + P[i + 2*NTOK*XDN] + P[i + 3*NTOK*XDN];
    C[i] = v;
}

// ---------------- selective scan, chunked smem staging -------------------
// Block: 16 channels x full sequence; chunk T=64, double-buffered cp.async.
__global__ void __launch_bounds__(256) scan_kernel(const float* __restrict__ delta,
                                                   const float* __restrict__ u,
                                                   const float* __restrict__ xdbl,
                                                   const float* __restrict__ xz,
                                                   const float* __restrict__ A_log,
                                                   const float* __restrict__ D_skip,
                                                   float* __restrict__ y)
{
    __shared__ float sD[2][64*16];
    __shared__ float sU[2][64*16];
    __shared__ float sZ[2][64*16];
    __shared__ float sBC[2][64*32];

    int b    = blockIdx.y;
    int tid  = threadIdx.x;
    int warp = tid>>5;
    int lane = tid&31;
    int half = lane>>4;
    int s    = lane&15;
    int dd   = warp*2 + half;
    int d0   = blockIdx.x*16;
    int d    = d0 + dd;

    float Aval = -expf(A_log[(size_t)d*DSTATE + s]);
    float Dv   = D_skip[d];

    const int T = 64, NC = SEQ/T;
    int srow = tid>>2, sc4 = tid&3;

    auto stage = [&](int c, int p){
        size_t tok = (size_t)(b*SEQ + c*T + srow);
        cp16(&sD[p][srow*16 + sc4*4], delta + tok*DINNER + d0 + sc4*4);
        cp16(&sU[p][srow*16 + sc4*4], u     + tok*DINNER + d0 + sc4*4);
        cp16(&sZ[p][srow*16 + sc4*4], xz    + tok*(2*DINNER) + DINNER + d0 + sc4*4);
        #pragma unroll
        for (int j=0;j<2;j++){
            int idx = tid + j*256;
            int r2 = idx>>3, c8 = idx&7;
            cp16(&sBC[p][r2*32 + c8*4],
                 xdbl + (size_t)(b*SEQ + c*T + r2)*XDN + DTRANK + c8*4);
        }
    };

    stage(0,0); cp_commit();
    stage(1,1); cp_commit();

    float h = 0.f;
    for (int c=0; c<NC; c++){
        int p = c & 1;
        asm volatile("cp.async.wait_group 1;\n");
        __syncthreads();
        size_t yb = (size_t)(b*SEQ + c*T)*DINNER + d;
        #pragma unroll 4
        for (int t=0; t<T; t++){
            float dlt = sD[p][t*16 + dd];
            float uu  = sU[p][t*16 + dd];
            float Bv  = sBC[p][t*32 + s];
            float Cv  = sBC[p][t*32 + 16 + s];
            float dA  = __expf(dlt * Aval);
            h = fmaf(dA, h, (dlt*uu)*Bv);
            float yp = h * Cv;
            yp += __shfl_xor_sync(0xffffffffu, yp, 1);
            yp += __shfl_xor_sync(0xffffffffu, yp, 2);
            yp += __shfl_xor_sync(0xffffffffu, yp, 4);
            yp += __shfl_xor_sync(0xffffffffu, yp, 8);
            if (s == 0){
                float zz = sZ[p][t*16 + dd];
                y[yb + (size_t)t*DINNER] = f2tf_f((yp + uu*Dv) * silu_f(zz));
            }
        }
        __syncthreads();
        if (c+2 < NC) stage(c+2, p);
        cp_commit();
    }
}

// ---------------- launch ----------------
extern "C" void kernel_launch(void* const* d_in, const int* in_sizes, int n_in,
                              void* d_out, int out_size)
{
    const float* x      = (const float*)d_in[0];
    const float* ln_w   = (const float*)d_in[1];
    const float* ln_b   = (const float*)d_in[2];
    const float* W_in   = (const float*)d_in[3];
    const float* conv_w = (const float*)d_in[4];
    const float* conv_b = (const float*)d_in[5];
    const float* W_x    = (const float*)d_in[6];
    const float* W_dt   = (const float*)d_in[7];
    const float* b_dt   = (const float*)d_in[8];
    const float* A_log  = (const float*)d_in[9];
    const float* D_skip = (const float*)d_in[10];
    const float* W_out  = (const float*)d_in[11];
    float* out = (float*)d_out;

    float *xn, *xz, *u, *xpart, *xdbl, *delta, *y, *Wi, *Wo;
    cudaGetSymbolAddress((void**)&xn,    g_xn);
    cudaGetSymbolAddress((void**)&xz,    g_xz);
    cudaGetSymbolAddress((void**)&u,     g_u);
    cudaGetSymbolAddress((void**)&xpart, g_xpart);
    cudaGetSymbolAddress((void**)&xdbl,  g_xdbl);
    cudaGetSymbolAddress((void**)&delta, g_delta);
    cudaGetSymbolAddress((void**)&y,     g_y);
    cudaGetSymbolAddress((void**)&Wi,    g_Wi);
    cudaGetSymbolAddress((void**)&Wo,    g_Wo);

    cudaFuncSetAttribute(tf32gemm<0>, cudaFuncAttributeMaxDynamicSharedMemorySize, GSMEM);
    cudaFuncSetAttribute(tf32gemm<2>, cudaFuncAttributeMaxDynamicSharedMemorySize, GSMEM);

    // 0) weight tf32 pre-round
    round_tf32<<<(DMODEL*2*DINNER/4)/256, 256>>>(W_in, Wi, DMODEL*2*DINNER);
    round_tf32<<<(DINNER*DMODEL/4)/256, 256>>>(W_out, Wo, DINNER*DMODEL);

    // 1) LayerNorm (tf32-rounded out)
    ln_kernel<<<NTOK, 256>>>(x, ln_w, ln_b, xn);

    // 2) xz = xn @ W_in   [4096 x 4096 x 1024]
    tf32gemm<0><<<dim3((2*DINNER)/128, NTOK/128), 256, GSMEM>>>(
        xn, Wi, xz, DMODEL, DMODEL, 2*DINNER, 2*DINNER, nullptr, 0);

    // 3) depthwise causal conv + silu
    conv_silu_kernel<<<(NTOK*(DINNER/4))/256, 256>>>(xz, conv_w, conv_b, u);

    // 4) x_dbl = u @ W_x  (split-K x4 + reduce)
    gemm_xdbl_part<<<dim3(NTOK/32, 4), 256>>>(u, W_x, xpart);
    xdbl_reduce<<<(NTOK*XDN)/256, 256>>>(xpart, xdbl);

    // 5) delta = softplus(dt @ W_dt + b_dt)  (exact fp32)
    sgemm_sp<<<dim3(DINNER/128, NTOK/128), 256>>>(
        xdbl, W_dt, delta, DTRANK, XDN, DINNER, DINNER, b_dt);

    // 6) selective scan + gating -> y (tf32-rounded)
    scan_kernel<<<dim3(DINNER/16, BATCH), 256>>>(delta, u, xdbl, xz, A_log, D_skip, y);

    // 7) out = gelu(y @ W_out) + x  [4096 x 1024 x 2048]
    tf32gemm<2><<<dim3(DMODEL/128, NTOK/128), 256, GSMEM>>>(
        y, Wo, out, DINNER, DINNER, DMODEL, DMODEL, x, DMODEL);
}

// round 9
// speedup vs baseline: 3.3986x; 1.0008x over previous
#include <cuda_runtime.h>
#include <cstdint>
#include <math.h>

#define BATCH  2
#define SEQ    2048
#define DMODEL 1024
#define DINNER 2048
#define DSTATE 16
#define DTRANK 64
#define NTOK   (BATCH*SEQ)
#define XDN    96

// ---------------- scratch (static device globals; no allocation) ----------
__device__ float g_xn[NTOK*DMODEL];            // tf32-rounded
__device__ float g_xz[NTOK*2*DINNER];
__device__ float g_u[NTOK*DINNER];
__device__ float g_xpart[4*NTOK*XDN];
__device__ float g_xdbl[NTOK*XDN];
__device__ float g_delta[NTOK*DINNER];
__device__ float g_y[NTOK*DINNER];             // tf32-rounded
__device__ float g_Wi[DMODEL*2*DINNER];        // tf32-rounded W_in
__device__ float g_Wo[DINNER*DMODEL];          // tf32-rounded W_out

// ---------------- helpers ----------------
__device__ __forceinline__ float softplus_f(float x){
    return (x > 20.f) ? x : log1pf(expf(x));
}
__device__ __forceinline__ float gelu_f(float x){
    return 0.5f * x * (1.f + erff(x * 0.70710678118654752440f));
}
__device__ __forceinline__ float silu_f(float x){
    return x * (1.f / (1.f + __expf(-x)));
}
__device__ __forceinline__ float f2tf_f(float x){
    unsigned u; asm("cvt.rna.tf32.f32 %0, %1;" : "=r"(u) : "f"(x));
    return __uint_as_float(u);
}
__device__ __forceinline__ void mma_tf32(float c[4], const unsigned a[4], const unsigned b[2]){
    asm volatile("mma.sync.aligned.m16n8k8.row.col.f32.tf32.tf32.f32 "
        "{%0,%1,%2,%3},{%4,%5,%6,%7},{%8,%9},{%0,%1,%2,%3};"
        : "+f"(c[0]), "+f"(c[1]), "+f"(c[2]), "+f"(c[3])
        : "r"(a[0]), "r"(a[1]), "r"(a[2]), "r"(a[3]), "r"(b[0]), "r"(b[1]));
}
__device__ __forceinline__ void cp16(void* smem, const void* g){
    unsigned saddr = (unsigned)__cvta_generic_to_shared(smem);
    asm volatile("cp.async.cg.shared.global [%0], [%1], 16;\n" :: "r"(saddr), "l"(g));
}
__device__ __forceinline__ void cp_commit(){ asm volatile("cp.async.commit_group;\n"); }

// ---------------- weight tf32 pre-round ----------------
__global__ void __launch_bounds__(256) round_tf32(const float* __restrict__ in,
                                                  float* __restrict__ out, int n)
{
    int i = (blockIdx.x*256 + threadIdx.x)*4;
    if (i < n){
        float4 v = *(const float4*)(in + i);
        v.x = f2tf_f(v.x); v.y = f2tf_f(v.y);
        v.z = f2tf_f(v.z); v.w = f2tf_f(v.w);
        *(float4*)(out + i) = v;
    }
}

// ---------------- LayerNorm (tf32-rounded out) ----------------
__global__ void __launch_bounds__(256) ln_kernel(const float* __restrict__ x,
                                                 const float* __restrict__ w,
                                                 const float* __restrict__ b,
                                                 float* __restrict__ out)
{
    int row = blockIdx.x;
    int tid = threadIdx.x;
    const float4* xr = reinterpret_cast<const float4*>(x + (size_t)row*DMODEL);
    float4 v = xr[tid];
    float s = v.x+v.y+v.z+v.w;
    float q = v.x*v.x+v.y*v.y+v.z*v.z+v.w*v.w;
    #pragma unroll
    for (int o=16;o>0;o>>=1){
        s += __shfl_down_sync(0xffffffffu, s, o);
        q += __shfl_down_sync(0xffffffffu, q, o);
    }
    __shared__ float ss[8], sq[8];
    __shared__ float mu_s, inv_s;
    int wp = tid>>5, ln = tid&31;
    if (ln==0){ ss[wp]=s; sq[wp]=q; }
    __syncthreads();
    if (tid==0){
        float ts=0.f, tq=0.f;
        #pragma unroll
        for (int i=0;i<8;i++){ ts+=ss[i]; tq+=sq[i]; }
        float mu  = ts * (1.f/DMODEL);
        float var = tq * (1.f/DMODEL) - mu*mu;
        mu_s = mu; inv_s = rsqrtf(var + 1e-5f);
    }
    __syncthreads();
    float mu = mu_s, inv = inv_s;
    float4 wv = reinterpret_cast<const float4*>(w)[tid];
    float4 bv = reinterpret_cast<const float4*>(b)[tid];
    float4 o;
    o.x = f2tf_f((v.x-mu)*inv*wv.x + bv.x);
    o.y = f2tf_f((v.y-mu)*inv*wv.y + bv.y);
    o.z = f2tf_f((v.z-mu)*inv*wv.z + bv.z);
    o.w = f2tf_f((v.w-mu)*inv*wv.w + bv.w);
    reinterpret_cast<float4*>(out + (size_t)row*DMODEL)[tid] = o;
}

// ======== TF32 GEMM v2: 128x128, 8 warps, 3-stage cp.async, no in-loop cvt
// C[M,N] = A[M,K] @ B[K,N], row-major, operands pre-rounded to tf32.
// EPI: 0 plain, 2 gelu(acc)+res
#define AS_LD 20
#define BS_LD 136
#define ASTG  (128*AS_LD)     /* floats per A stage: 2560 */
#define BSTG  (16*BS_LD)      /* floats per B stage: 2176 */
#define GSMEM ((3*(ASTG+BSTG))*4)   /* 56832 bytes */

template<int EPI>
__global__ void __launch_bounds__(256,2) tf32gemm(const float* __restrict__ A,
                                                  const float* __restrict__ B,
                                                  float* __restrict__ C,
                                                  int K, int lda, int ldb, int ldc,
                                                  const float* __restrict__ res,
                                                  int ldres)
{
    extern __shared__ float smem[];
    float* As = smem;                 // 3 stages
    float* Bs = smem + 3*ASTG;        // 3 stages

    const int tid  = threadIdx.x;
    const int warp = tid>>5, lane = tid&31;
    const int wm = warp>>2, wn = warp&3;
    const int g  = lane>>2, tg = lane&3;
    const int bm = blockIdx.y*128, bn = blockIdx.x*128;

    const float* aptr[2]; int asm_[2];
    const float* bptr[2]; int bsm_[2];
    #pragma unroll
    for (int s=0;s<2;s++){
        int c  = tid + s*256;
        int m  = c>>2, k4 = (c&3)*4;
        aptr[s] = A + (size_t)(bm+m)*lda + k4;
        asm_[s] = m*AS_LD + k4;
        int kr = c>>5, n4 = (c&31)*4;
        bptr[s] = B + (size_t)kr*ldb + bn + n4;
        bsm_[s] = kr*BS_LD + n4;
    }

    float acc[4][4][4];
    #pragma unroll
    for (int i=0;i<4;i++)
        #pragma unroll
        for (int j=0;j<4;j++)
            #pragma unroll
            for (int r=0;r<4;r++) acc[i][j][r]=0.f;

    const int nkt = K/16;
    // prologue: stages 0,1,2
    #pragma unroll
    for (int st=0; st<3; st++){
        int k0 = st*16;
        #pragma unroll
        for (int s=0;s<2;s++){
            cp16(&As[st*ASTG + asm_[s]], aptr[s] + k0);
            cp16(&Bs[st*BSTG + bsm_[s]], bptr[s] + (size_t)k0*ldb);
        }
        cp_commit();
    }

    int buf = 0;
    for (int kt=0; kt<nkt; kt++){
        asm volatile("cp.async.wait_group 2;\n");
        __syncthreads();
        const float* as = As + buf*ASTG;
        const float* bs = Bs + buf*BSTG;
        #pragma unroll
        for (int kg=0; kg<16; kg+=8){
            unsigned af[4][4], bf[4][2];
            #pragma unroll
            for (int i=0;i<4;i++){
                int mr = wm*64 + i*16 + g;
                af[i][0] = __float_as_uint(as[ mr   *AS_LD + kg+tg  ]);
                af[i][1] = __float_as_uint(as[(mr+8)*AS_LD + kg+tg  ]);
                af[i][2] = __float_as_uint(as[ mr   *AS_LD + kg+tg+4]);
                af[i][3] = __float_as_uint(as[(mr+8)*AS_LD + kg+tg+4]);
            }
            #pragma unroll
            for (int j=0;j<4;j++){
                int nc = wn*32 + j*8 + g;
                bf[j][0] = __float_as_uint(bs[(kg+tg  )*BS_LD + nc]);
                bf[j][1] = __float_as_uint(bs[(kg+tg+4)*BS_LD + nc]);
            }
            #pragma unroll
            for (int i=0;i<4;i++)
                #pragma unroll
                for (int j=0;j<4;j++)
                    mma_tf32(acc[i][j], af[i], bf[j]);
        }
        __syncthreads();
        if (kt+3 < nkt){
            int k0 = (kt+3)*16;
            #pragma unroll
            for (int s=0;s<2;s++){
                cp16(&As[buf*ASTG + asm_[s]], aptr[s] + k0);
                cp16(&Bs[buf*BSTG + bsm_[s]], bptr[s] + (size_t)k0*ldb);
            }
        }
        cp_commit();
        buf = (buf==2) ? 0 : buf+1;
    }

    #pragma unroll
    for (int i=0;i<4;i++){
        #pragma unroll
        for (int j=0;j<4;j++){
            int r = bm + wm*64 + i*16 + g;
            int c = bn + wn*32 + j*8 + tg*2;
            float v0=acc[i][j][0], v1=acc[i][j][1];
            float v2=acc[i][j][2], v3=acc[i][j][3];
            if (EPI==2){
                v0 = gelu_f(v0) + res[(size_t)r*ldres + c];
                v1 = gelu_f(v1) + res[(size_t)r*ldres + c + 1];
                v2 = gelu_f(v2) + res[(size_t)(r+8)*ldres + c];
                v3 = gelu_f(v3) + res[(size_t)(r+8)*ldres + c + 1];
            }
            *(float2*)(C + (size_t)r*ldc + c)     = make_float2(v0,v1);
            *(float2*)(C + (size_t)(r+8)*ldc + c) = make_float2(v2,v3);
        }
    }
}

// ---------------- SGEMM 128x128x8 fp32 (delta GEMM, exact) ---------------
__global__ void __launch_bounds__(256) sgemm_sp(const float* __restrict__ A,
                                                const float* __restrict__ B,
                                                float* __restrict__ C,
                                                int K, int lda, int ldb, int ldc,
                                                const float* __restrict__ bias)
{
    __shared__ float As[8][128];
    __shared__ float Bs[8][128];
    const int tid = threadIdx.x;
    const int bm = blockIdx.y*128, bn = blockIdx.x*128;
    const int ty = tid>>4, tx = tid&15;
    const int arow = tid>>1,  acol = (tid&1)*4;
    const int brow = tid>>5,  bcol = (tid&31)*4;

    const float* Ap = A + (size_t)(bm+arow)*lda + acol;
    const float* Bp = B + (size_t)brow*ldb + bn + bcol;
    float4 af = *(const float4*)Ap;
    float4 bf = *(const float4*)Bp;

    float acc[8][8];
    #pragma unroll
    for (int i=0;i<8;i++)
        #pragma unroll
        for (int j=0;j<8;j++) acc[i][j]=0.f;

    for (int k0=0; k0<K; k0+=8){
        As[acol+0][arow]=af.x; As[acol+1][arow]=af.y;
        As[acol+2][arow]=af.z; As[acol+3][arow]=af.w;
        *(float4*)&Bs[brow][bcol] = bf;
        __syncthreads();
        if (k0+8 < K){
            af = *(const float4*)(Ap + (k0+8));
            bf = *(const float4*)(Bp + (size_t)(k0+8)*ldb);
        }
        #pragma unroll
        for (int k=0;k<8;k++){
            float ar[8], br[8];
            *(float4*)&ar[0] = *(const float4*)&As[k][ty*8];
            *(float4*)&ar[4] = *(const float4*)&As[k][ty*8+4];
            *(float4*)&br[0] = *(const float4*)&Bs[k][tx*8];
            *(float4*)&br[4] = *(const float4*)&Bs[k][tx*8+4];
            #pragma unroll
            for (int i=0;i<8;i++)
                #pragma unroll
                for (int j=0;j<8;j++)
                    acc[i][j] = fmaf(ar[i], br[j], acc[i][j]);
        }
        __syncthreads();
    }
    #pragma unroll
    for (int i=0;i<8;i++){
        int r = bm + ty*8 + i;
        float vals[8];
        #pragma unroll
        for (int j=0;j<8;j++)
            vals[j] = softplus_f(acc[i][j] + bias[bn + tx*8 + j]);
        float* cp_ = C + (size_t)r*ldc + bn + tx*8;
        *(float4*)cp_     = *(float4*)&vals[0];
        *(float4*)(cp_+4) = *(float4*)&vals[4];
    }
}

// ---------------- depthwise causal conv (width 4) + SiLU -----------------
__global__ void __launch_bounds__(256) conv_silu_kernel(const float* __restrict__ xz,
                                                        const float* __restrict__ cw,
                                                        const float* __restrict__ cb,
                                                        float* __restrict__ u)
{
    int lin = blockIdx.x*256 + threadIdx.x;
    int d4  = lin & (DINNER/4 - 1);
    int tok = lin >> 9;
    int t   = tok & (SEQ-1);
    int d   = d4*4;

    float4 acc = *(const float4*)(cb + d);
    float w0[4], w1[4], w2[4], w3[4];
    *(float4*)w0 = *(const float4*)(cw + (size_t)(d+0)*4);
    *(float4*)w1 = *(const float4*)(cw + (size_t)(d+1)*4);
    *(float4*)w2 = *(const float4*)(cw + (size_t)(d+2)*4);
    *(float4*)w3 = *(const float4*)(cw + (size_t)(d+3)*4);

    const float* base = xz + (size_t)tok*(2*DINNER) + d;
    #pragma unroll
    for (int j=0;j<4;j++){
        int tt = t - 3 + j;
        if (tt >= 0){
            float4 xv = *(const float4*)(base + (ptrdiff_t)(j-3)*(2*DINNER));
            acc.x = fmaf(xv.x, w0[j], acc.x);
            acc.y = fmaf(xv.y, w1[j], acc.y);
            acc.z = fmaf(xv.z, w2[j], acc.z);
            acc.w = fmaf(xv.w, w3[j], acc.w);
        }
    }
    float4 o;
    o.x = silu_f(acc.x); o.y = silu_f(acc.y);
    o.z = silu_f(acc.z); o.w = silu_f(acc.w);
    *(float4*)(u + (size_t)tok*DINNER + d) = o;
}

// ---------------- xdbl split-K: partial[kb] = u[:,kb*512:+512] @ W_x -----
__global__ void __launch_bounds__(256) gemm_xdbl_part(const float* __restrict__ A,
                                                      const float* __restrict__ B,
                                                      float* __restrict__ P)
{
    __shared__ float As[32][36];
    __shared__ float Bs[32][100];
    int tid = threadIdx.x;
    int bm  = blockIdx.x*32;
    int kb  = blockIdx.y;
    int ty  = tid>>4, tx = tid&15;
    float acc[2][6];
    #pragma unroll
    for (int i=0;i<2;i++)
        #pragma unroll
        for (int j=0;j<6;j++) acc[i][j]=0.f;

    for (int k0=kb*512; k0<(kb+1)*512; k0+=32){
        {
            int m = tid>>3, k4 = (tid&7)*4;
            float4 v = *(const float4*)(A + (size_t)(bm+m)*DINNER + k0 + k4);
            As[k4+0][m]=v.x; As[k4+1][m]=v.y; As[k4+2][m]=v.z; As[k4+3][m]=v.w;
        }
        #pragma unroll
        for (int i=0;i<3;i++){
            int lin = tid + i*256;
            int kr = lin/24, c4 = (lin%24)*4;
            float4 v = *(const float4*)(B + (size_t)(k0+kr)*XDN + c4);
            *(float4*)&Bs[kr][c4] = v;
        }
        __syncthreads();
        #pragma unroll
        for (int k=0;k<32;k++){
            float a[2], bb[6];
            #pragma unroll
            for (int i=0;i<2;i++) a[i]=As[k][ty*2+i];
            #pragma unroll
            for (int j=0;j<6;j++) bb[j]=Bs[k][tx*6+j];
            #pragma unroll
            for (int i=0;i<2;i++)
                #pragma unroll
                for (int j=0;j<6;j++)
                    acc[i][j] = fmaf(a[i], bb[j], acc[i][j]);
        }
        __syncthreads();
    }
    float* out = P + (size_t)kb*NTOK*XDN;
    #pragma unroll
    for (int i=0;i<2;i++)
        #pragma unroll
        for (int j=0;j<6;j++)
            out[(size_t)(bm+ty*2+i)*XDN + tx*6 + j] = acc[i][j];
}

__global__ void __launch_bounds__(256) xdbl_reduce(const float* __restrict__ P,
                                                   float* __restrict__ C)
{
    int i = blockIdx.x*256 + threadIdx.x;   // over NTOK*XDN
    float v = P[i] + P[i + NTOK*XDN] + P[i + 2*NTOK*XDN] + P[i + 3*NTOK*XDN];
    C[i] = v;
}

// ---------------- selective scan, chunked smem staging -------------------
// Block: 16 channels x full sequence; chunk T=64, double-buffered cp.async.
__global__ void __launch_bounds__(256) scan_kernel(const float* __restrict__ delta,
                                                   const float* __restrict__ u,
                                                   const float* __restrict__ xdbl,
                                                   const float* __restrict__ xz,
                                                   const float* __restrict__ A_log,
                                                   const float* __restrict__ D_skip,
                                                   float* __restrict__ y)
{
    __shared__ float sD[2][64*16];
    __shared__ float sU[2][64*16];
    __shared__ float sZ[2][64*16];
    __shared__ float sBC[2][64*32];

    int b    = blockIdx.y;
    int tid  = threadIdx.x;
    int warp = tid>>5;
    int lane = tid&31;
    int half = lane>>4;
    int s    = lane&15;
    int dd   = warp*2 + half;
    int d0   = blockIdx.x*16;
    int d    = d0 + dd;

    float Aval = -expf(A_log[(size_t)d*DSTATE + s]);
    float Dv   = D_skip[d];

    const int T = 64, NC = SEQ/T;
    int srow = tid>>2, sc4 = tid&3;

    auto stage = [&](int c, int p){
        size_t tok = (size_t)(b*SEQ + c*T + srow);
        cp16(&sD[p][srow*16 + sc4*4], delta + tok*DINNER + d0 + sc4*4);
        cp16(&sU[p][srow*16 + sc4*4], u     + tok*DINNER + d0 + sc4*4);
        cp16(&sZ[p][srow*16 + sc4*4], xz    + tok*(2*DINNER) + DINNER + d0 + sc4*4);
        #pragma unroll
        for (int j=0;j<2;j++){
            int idx = tid + j*256;
            int r2 = idx>>3, c8 = idx&7;
            cp16(&sBC[p][r2*32 + c8*4],
                 xdbl + (size_t)(b*SEQ + c*T + r2)*XDN + DTRANK + c8*4);
        }
    };

    stage(0,0); cp_commit();
    stage(1,1); cp_commit();

    float h = 0.f;
    for (int c=0; c<NC; c++){
        int p = c & 1;
        asm volatile("cp.async.wait_group 1;\n");
        __syncthreads();
        size_t yb = (size_t)(b*SEQ + c*T)*DINNER + d;
        #pragma unroll 4
        for (int t=0; t<T; t++){
            float dlt = sD[p][t*16 + dd];
            float uu  = sU[p][t*16 + dd];
            float Bv  = sBC[p][t*32 + s];
            float Cv  = sBC[p][t*32 + 16 + s];
            float dA  = __expf(dlt * Aval);
            h = fmaf(dA, h, (dlt*uu)*Bv);
            float yp = h * Cv;
            yp += __shfl_xor_sync(0xffffffffu, yp, 1);
            yp += __shfl_xor_sync(0xffffffffu, yp, 2);
            yp += __shfl_xor_sync(0xffffffffu, yp, 4);
            yp += __shfl_xor_sync(0xffffffffu, yp, 8);
            if (s == 0){
                float zz = sZ[p][t*16 + dd];
                y[yb + (size_t)t*DINNER] = f2tf_f((yp + uu*Dv) * silu_f(zz));
            }
        }
        __syncthreads();
        if (c+2 < NC) stage(c+2, p);
        cp_commit();
    }
}

// ---------------- launch ----------------
extern "C" void kernel_launch(void* const* d_in, const int* in_sizes, int n_in,
                              void* d_out, int out_size)
{
    const float* x      = (const float*)d_in[0];
    const float* ln_w   = (const float*)d_in[1];
    const float* ln_b   = (const float*)d_in[2];
    const float* W_in   = (const float*)d_in[3];
    const float* conv_w = (const float*)d_in[4];
    const float* conv_b = (const float*)d_in[5];
    const float* W_x    = (const float*)d_in[6];
    const float* W_dt   = (const float*)d_in[7];
    const float* b_dt   = (const float*)d_in[8];
    const float* A_log  = (const float*)d_in[9];
    const float* D_skip = (const float*)d_in[10];
    const float* W_out  = (const float*)d_in[11];
    float* out = (float*)d_out;

    float *xn, *xz, *u, *xpart, *xdbl, *delta, *y, *Wi, *Wo;
    cudaGetSymbolAddress((void**)&xn,    g_xn);
    cudaGetSymbolAddress((void**)&xz,    g_xz);
    cudaGetSymbolAddress((void**)&u,     g_u);
    cudaGetSymbolAddress((void**)&xpart, g_xpart);
    cudaGetSymbolAddress((void**)&xdbl,  g_xdbl);
    cudaGetSymbolAddress((void**)&delta, g_delta);
    cudaGetSymbolAddress((void**)&y,     g_y);
    cudaGetSymbolAddress((void**)&Wi,    g_Wi);
    cudaGetSymbolAddress((void**)&Wo,    g_Wo);

    cudaFuncSetAttribute(tf32gemm<0>, cudaFuncAttributeMaxDynamicSharedMemorySize, GSMEM);
    cudaFuncSetAttribute(tf32gemm<2>, cudaFuncAttributeMaxDynamicSharedMemorySize, GSMEM);

    // 0) weight tf32 pre-round
    round_tf32<<<(DMODEL*2*DINNER/4)/256, 256>>>(W_in, Wi, DMODEL*2*DINNER);
    round_tf32<<<(DINNER*DMODEL/4)/256, 256>>>(W_out, Wo, DINNER*DMODEL);

    // 1) LayerNorm (tf32-rounded out)
    ln_kernel<<<NTOK, 256>>>(x, ln_w, ln_b, xn);

    // 2) xz = xn @ W_in   [4096 x 4096 x 1024]
    tf32gemm<0><<<dim3((2*DINNER)/128, NTOK/128), 256, GSMEM>>>(
        xn, Wi, xz, DMODEL, DMODEL, 2*DINNER, 2*DINNER, nullptr, 0);

    // 3) depthwise causal conv + silu
    conv_silu_kernel<<<(NTOK*(DINNER/4))/256, 256>>>(xz, conv_w, conv_b, u);

    // 4) x_dbl = u @ W_x  (split-K x4 + reduce)
    gemm_xdbl_part<<<dim3(NTOK/32, 4), 256>>>(u, W_x, xpart);
    xdbl_reduce<<<(NTOK*XDN)/256, 256>>>(xpart, xdbl);

    // 5) delta = softplus(dt @ W_dt + b_dt)  (exact fp32)
    sgemm_sp<<<dim3(DINNER/128, NTOK/128), 256>>>(
        xdbl, W_dt, delta, DTRANK, XDN, DINNER, DINNER, b_dt);

    // 6) selective scan + gating -> y (tf32-rounded)
    scan_kernel<<<dim3(DINNER/16, BATCH), 256>>>(delta, u, xdbl, xz, A_log, D_skip, y);

    // 7) out = gelu(y @ W_out) + x  [4096 x 1024 x 2048]
    tf32gemm<2><<<dim3(DMODEL/128, NTOK/128), 256, GSMEM>>>(
        y, Wo, out, DINNER, DINNER, DMODEL, DMODEL, x, DMODEL);
}